// round 1
// baseline (speedup 1.0000x reference)
#include <cuda_runtime.h>

#define BB     2
#define LL     2048
#define LTXT   1024
#define DMODEL 512
#define NHEAD  8
#define DHEAD  64

// Scratch (device globals; no allocations allowed)
__device__ float g_q[BB*NHEAD*LL*DHEAD];
__device__ float g_k[BB*NHEAD*LL*DHEAD];
__device__ float g_v[BB*NHEAD*LL*DHEAD];
__device__ float g_attn[BB*LL*DMODEL];
__device__ float g_coef[BB*LL];

// ---------------------------------------------------------------------------
// Mask -> per-position post-softmax coefficient. coef==0 iff position masked.
// ---------------------------------------------------------------------------
__global__ void coef_kernel(const float* __restrict__ tm, const float* __restrict__ am)
{
    int b = blockIdx.x;
    int t = threadIdx.x;              // 1024 threads
    float tv = tm[b*LTXT + t];
    float av = am[b*LTXT + t];
    float ts = tv, as_ = av;
    #pragma unroll
    for (int o = 16; o; o >>= 1) {
        ts  += __shfl_xor_sync(0xffffffffu, ts,  o);
        as_ += __shfl_xor_sync(0xffffffffu, as_, o);
    }
    __shared__ float st[32], sa[32];
    int warp = t >> 5, lane = t & 31;
    if (lane == 0) { st[warp] = ts; sa[warp] = as_; }
    __syncthreads();
    if (warp == 0) {
        ts = st[lane]; as_ = sa[lane];
        #pragma unroll
        for (int o = 16; o; o >>= 1) {
            ts  += __shfl_xor_sync(0xffffffffu, ts,  o);
            as_ += __shfl_xor_sync(0xffffffffu, as_, o);
        }
        if (lane == 0) { st[0] = ts; sa[0] = as_; }
    }
    __syncthreads();
    float tsum = st[0], asum = sa[0], tot = tsum + asum;
    g_coef[b*LL + t]        = tv * (tot / (2.0f * tsum));
    g_coef[b*LL + LTXT + t] = av * (tot / (2.0f * asum));
}

// ---------------------------------------------------------------------------
// SGEMM: Y = X @ W^T + bias.  M=4096, N=512, K=512 fixed.
// headsplit=1: write Y as [B, H, L, Dh] (for Q/K/V). Otherwise [M, 512].
// ---------------------------------------------------------------------------
__global__ void __launch_bounds__(256) sgemm_kernel(
    const float* __restrict__ X, const float* __restrict__ W,
    const float* __restrict__ bias, float* __restrict__ Y, int headsplit)
{
    __shared__ float As[16][68];
    __shared__ float Bs[16][68];
    const int tid = threadIdx.x;
    const int tx = tid & 15, ty = tid >> 4;
    const int m0 = blockIdx.y * 64, n0 = blockIdx.x * 64;
    const int lr = tid >> 2;            // 0..63: row within tile
    const int lk = (tid & 3) << 2;      // 0,4,8,12: k offset

    float acc[4][4] = {};
    for (int k0 = 0; k0 < DMODEL; k0 += 16) {
        float4 a4 = *(const float4*)(X + (size_t)(m0 + lr) * DMODEL + k0 + lk);
        float4 b4 = *(const float4*)(W + (size_t)(n0 + lr) * DMODEL + k0 + lk);
        As[lk+0][lr] = a4.x; As[lk+1][lr] = a4.y; As[lk+2][lr] = a4.z; As[lk+3][lr] = a4.w;
        Bs[lk+0][lr] = b4.x; Bs[lk+1][lr] = b4.y; Bs[lk+2][lr] = b4.z; Bs[lk+3][lr] = b4.w;
        __syncthreads();
        #pragma unroll
        for (int kk = 0; kk < 16; kk++) {
            float a[4], b[4];
            #pragma unroll
            for (int i = 0; i < 4; i++) a[i] = As[kk][ty*4+i];
            #pragma unroll
            for (int j = 0; j < 4; j++) b[j] = Bs[kk][tx*4+j];
            #pragma unroll
            for (int i = 0; i < 4; i++)
                #pragma unroll
                for (int j = 0; j < 4; j++)
                    acc[i][j] = fmaf(a[i], b[j], acc[i][j]);
        }
        __syncthreads();
    }
    #pragma unroll
    for (int i = 0; i < 4; i++) {
        int row = m0 + ty*4 + i;
        #pragma unroll
        for (int j = 0; j < 4; j++) {
            int oc = n0 + tx*4 + j;
            float val = acc[i][j] + bias[oc];
            if (headsplit) {
                int bi = row >> 11, l = row & 2047;
                int h  = oc >> 6,  d = oc & 63;
                Y[(((size_t)(bi*NHEAD + h))*LL + l)*DHEAD + d] = val;
            } else {
                Y[(size_t)row * DMODEL + oc] = val;
            }
        }
    }
}

// ---------------------------------------------------------------------------
// Fused attention: flash-style, fp32, BM=BN=64, online softmax.
// coef folded into V at tile load; coef==0 doubles as pad mask.
// grid = (L/64, B*H), 256 threads (8 warps).
// ---------------------------------------------------------------------------
#define ATTN_SMEM ((4*64*65 + 5*64) * 4)

__global__ void __launch_bounds__(256) attn_kernel()
{
    extern __shared__ float sm[];
    float* Qs   = sm;                 // [64][65], prescaled by 1/8
    float* Ks   = Qs + 64*65;         // [64][65]
    float* Vs   = Ks + 64*65;         // [64][65], pre-multiplied by coef
    float* Ss   = Vs + 64*65;         // [64][65]: scores then P
    float* m_s  = Ss + 64*65;         // [64] running max
    float* l_s  = m_s + 64;           // [64] running denom
    float* sc_s = l_s + 64;           // [64] rescale factor
    float* qok  = sc_s + 64;          // [64] query coef (0 => masked)
    float* kok  = qok + 64;           // [64] key coef   (0 => masked)

    const int tid  = threadIdx.x;
    const int tx   = tid & 15, ty = tid >> 4;
    const int warp = tid >> 5, lane = tid & 31;
    const int bh   = blockIdx.y;      // b*8 + h
    const int bi   = bh >> 3;
    const int q0   = blockIdx.x * 64;

    const float* qbase = g_q + ((size_t)bh * LL + q0) * DHEAD;
    for (int idx = tid; idx < 64*64; idx += 256) {
        int r = idx >> 6, d = idx & 63;
        Qs[r*65 + d] = qbase[r*64 + d] * 0.125f;   // 1/sqrt(64)
        if (d == 0) qok[r] = g_coef[bi*LL + q0 + r];
    }
    if (tid < 64) { m_s[tid] = -1e30f; l_s[tid] = 0.0f; }

    float acc[4][4] = {};
    const float* kbase = g_k + (size_t)bh * LL * DHEAD;
    const float* vbase = g_v + (size_t)bh * LL * DHEAD;

    for (int k0 = 0; k0 < LL; k0 += 64) {
        __syncthreads();   // protect Ks/Vs/Ss reuse; also covers Q/m/l init
        for (int idx = tid; idx < 64*64; idx += 256) {
            int r = idx >> 6, d = idx & 63;
            float cf = g_coef[bi*LL + k0 + r];
            Ks[r*65 + d] = kbase[(size_t)(k0 + r)*64 + d];
            Vs[r*65 + d] = vbase[(size_t)(k0 + r)*64 + d] * cf;
            if (d == 0) kok[r] = cf;
        }
        __syncthreads();

        // S = (Q/8) K^T with masking
        float s[4][4] = {};
        #pragma unroll 8
        for (int d = 0; d < 64; d++) {
            float a[4], b[4];
            #pragma unroll
            for (int i = 0; i < 4; i++) a[i] = Qs[(ty*4+i)*65 + d];
            #pragma unroll
            for (int j = 0; j < 4; j++) b[j] = Ks[(tx*4+j)*65 + d];
            #pragma unroll
            for (int i = 0; i < 4; i++)
                #pragma unroll
                for (int j = 0; j < 4; j++)
                    s[i][j] = fmaf(a[i], b[j], s[i][j]);
        }
        #pragma unroll
        for (int i = 0; i < 4; i++) {
            bool qm = (qok[ty*4+i] != 0.0f);
            #pragma unroll
            for (int j = 0; j < 4; j++) {
                bool km = (kok[tx*4+j] != 0.0f);
                Ss[(ty*4+i)*65 + tx*4 + j] = (qm && km) ? s[i][j] : -10000.0f;
            }
        }
        __syncthreads();

        // online softmax: each warp owns 8 rows
        for (int r = 0; r < 8; r++) {
            int qr = warp*8 + r;
            float x1 = Ss[qr*65 + lane];
            float x2 = Ss[qr*65 + lane + 32];
            float mx = fmaxf(x1, x2);
            #pragma unroll
            for (int o = 16; o; o >>= 1) mx = fmaxf(mx, __shfl_xor_sync(0xffffffffu, mx, o));
            float mo = m_s[qr];
            float nm = fmaxf(mo, mx);
            float p1 = __expf(x1 - nm);
            float p2 = __expf(x2 - nm);
            Ss[qr*65 + lane]      = p1;
            Ss[qr*65 + lane + 32] = p2;
            float rs = p1 + p2;
            #pragma unroll
            for (int o = 16; o; o >>= 1) rs += __shfl_xor_sync(0xffffffffu, rs, o);
            if (lane == 0) {
                float sc = __expf(mo - nm);
                sc_s[qr] = sc;
                l_s[qr]  = l_s[qr]*sc + rs;
                m_s[qr]  = nm;
            }
        }
        __syncthreads();

        // acc = acc*scale + P @ (V*coef)
        #pragma unroll
        for (int i = 0; i < 4; i++) {
            float sc = sc_s[ty*4+i];
            #pragma unroll
            for (int j = 0; j < 4; j++) acc[i][j] *= sc;
        }
        #pragma unroll 8
        for (int kk = 0; kk < 64; kk++) {
            float p[4], vv[4];
            #pragma unroll
            for (int i = 0; i < 4; i++) p[i] = Ss[(ty*4+i)*65 + kk];
            #pragma unroll
            for (int j = 0; j < 4; j++) vv[j] = Vs[kk*65 + tx*4 + j];
            #pragma unroll
            for (int i = 0; i < 4; i++)
                #pragma unroll
                for (int j = 0; j < 4; j++)
                    acc[i][j] = fmaf(p[i], vv[j], acc[i][j]);
        }
    }

    const int h = bh & 7;
    #pragma unroll
    for (int i = 0; i < 4; i++) {
        int qr = ty*4 + i;
        float inv = 1.0f / l_s[qr];
        #pragma unroll
        for (int j = 0; j < 4; j++) {
            int d = tx*4 + j;
            g_attn[((size_t)(bi*LL + q0 + qr))*DMODEL + h*DHEAD + d] = acc[i][j] * inv;
        }
    }
}

// ---------------------------------------------------------------------------
extern "C" void kernel_launch(void* const* d_in, const int* in_sizes, int n_in,
                              void* d_out, int out_size)
{
    const float* q  = (const float*)d_in[0];
    const float* k  = (const float*)d_in[1];
    const float* v  = (const float*)d_in[2];
    const float* tm = (const float*)d_in[3];
    const float* am = (const float*)d_in[4];
    // d_in[5] = n_head (unused; hardcoded)
    const float* wq = (const float*)d_in[6];
    const float* bq = (const float*)d_in[7];
    const float* wk = (const float*)d_in[8];
    const float* bk = (const float*)d_in[9];
    const float* wv = (const float*)d_in[10];
    const float* bv = (const float*)d_in[11];
    const float* wo = (const float*)d_in[12];
    const float* bo = (const float*)d_in[13];
    float* out = (float*)d_out;

    float *gq, *gk, *gv, *gattn;
    cudaGetSymbolAddress((void**)&gq,    g_q);
    cudaGetSymbolAddress((void**)&gk,    g_k);
    cudaGetSymbolAddress((void**)&gv,    g_v);
    cudaGetSymbolAddress((void**)&gattn, g_attn);

    cudaFuncSetAttribute(attn_kernel, cudaFuncAttributeMaxDynamicSharedMemorySize, ATTN_SMEM);

    coef_kernel<<<2, 1024>>>(tm, am);
    dim3 gg(8, 64);
    sgemm_kernel<<<gg, 256>>>(q, wq, bq, gq, 1);
    sgemm_kernel<<<gg, 256>>>(k, wk, bk, gk, 1);
    sgemm_kernel<<<gg, 256>>>(v, wv, bv, gv, 1);
    attn_kernel<<<dim3(32, 16), 256, ATTN_SMEM>>>();
    sgemm_kernel<<<gg, 256>>>(gattn, wo, bo, out, 0);
}

// round 2
// speedup vs baseline: 2.5778x; 2.5778x over previous
#include <cuda_runtime.h>
#include <cstdint>

#define BB     2
#define LL     2048
#define LTXT   1024
#define DMODEL 512
#define NHEAD  8
#define DHEAD  64

// Scratch (device globals; no allocations allowed)
__device__ float g_q[BB*NHEAD*LL*DHEAD];
__device__ float g_k[BB*NHEAD*LL*DHEAD];
__device__ float g_v[BB*NHEAD*LL*DHEAD];
__device__ float g_attn[BB*LL*DMODEL];
__device__ float g_coef[BB*LL];

// ---------------------------------------------------------------------------
// Helpers: tf32 convert + m16n8k8 tf32 mma
// ---------------------------------------------------------------------------
__device__ __forceinline__ uint32_t f2tf(float x) {
    uint32_t r;
    asm("cvt.rna.tf32.f32 %0, %1;" : "=r"(r) : "f"(x));
    return r;
}
__device__ __forceinline__ void mma8(float* c,
    uint32_t a0, uint32_t a1, uint32_t a2, uint32_t a3,
    uint32_t b0, uint32_t b1)
{
    asm("mma.sync.aligned.m16n8k8.row.col.f32.tf32.tf32.f32 "
        "{%0,%1,%2,%3},{%4,%5,%6,%7},{%8,%9},{%0,%1,%2,%3};"
        : "+f"(c[0]), "+f"(c[1]), "+f"(c[2]), "+f"(c[3])
        : "r"(a0), "r"(a1), "r"(a2), "r"(a3), "r"(b0), "r"(b1));
}

// ---------------------------------------------------------------------------
// Mask -> per-position post-softmax coefficient. coef==0 iff position masked.
// ---------------------------------------------------------------------------
__global__ void coef_kernel(const float* __restrict__ tm, const float* __restrict__ am)
{
    int b = blockIdx.x;
    int t = threadIdx.x;              // 1024 threads
    float tv = tm[b*LTXT + t];
    float av = am[b*LTXT + t];
    float ts = tv, as_ = av;
    #pragma unroll
    for (int o = 16; o; o >>= 1) {
        ts  += __shfl_xor_sync(0xffffffffu, ts,  o);
        as_ += __shfl_xor_sync(0xffffffffu, as_, o);
    }
    __shared__ float st[32], sa[32];
    int warp = t >> 5, lane = t & 31;
    if (lane == 0) { st[warp] = ts; sa[warp] = as_; }
    __syncthreads();
    if (warp == 0) {
        ts = st[lane]; as_ = sa[lane];
        #pragma unroll
        for (int o = 16; o; o >>= 1) {
            ts  += __shfl_xor_sync(0xffffffffu, ts,  o);
            as_ += __shfl_xor_sync(0xffffffffu, as_, o);
        }
        if (lane == 0) { st[0] = ts; sa[0] = as_; }
    }
    __syncthreads();
    float tsum = st[0], asum = sa[0], tot = tsum + asum;
    g_coef[b*LL + t]        = tv * (tot / (2.0f * tsum));
    g_coef[b*LL + LTXT + t] = av * (tot / (2.0f * asum));
}

// ---------------------------------------------------------------------------
// TF32 tensor-core GEMM: Y = X @ W^T + bias.  M=4096, N=512, K=512.
// Block: 64x64 tile, 128 threads (4 warps), warp computes 16x64.
// headsplit=1: Y written as [B,H,L,Dh].
// ---------------------------------------------------------------------------
#define GP 36   // smem pitch (floats): (4r + k) % 32 distinct -> conflict-free frags

__global__ void __launch_bounds__(128) sgemm_tc(
    const float* __restrict__ X, const float* __restrict__ W,
    const float* __restrict__ bias, float* __restrict__ Y, int headsplit)
{
    __shared__ uint32_t Xs[64*GP];
    __shared__ uint32_t Ws[64*GP];
    const int tid  = threadIdx.x;
    const int warp = tid >> 5, lane = tid & 31;
    const int qr = lane >> 2, qc = lane & 3;
    const int m0 = blockIdx.y * 64, n0 = blockIdx.x * 64;
    const int wrow = warp * 16;

    float c[8][4] = {};

    for (int k0 = 0; k0 < DMODEL; k0 += 32) {
        __syncthreads();
        #pragma unroll
        for (int i = 0; i < 4; i++) {
            int s  = tid + i*128;          // 0..511 float4 slots
            int r  = s >> 3;
            int k4 = (s & 7) << 2;
            float4 x = *(const float4*)(X + (size_t)(m0 + r)*DMODEL + k0 + k4);
            float4 w = *(const float4*)(W + (size_t)(n0 + r)*DMODEL + k0 + k4);
            uint4 xb = make_uint4(f2tf(x.x), f2tf(x.y), f2tf(x.z), f2tf(x.w));
            uint4 wb = make_uint4(f2tf(w.x), f2tf(w.y), f2tf(w.z), f2tf(w.w));
            *(uint4*)(Xs + r*GP + k4) = xb;
            *(uint4*)(Ws + r*GP + k4) = wb;
        }
        __syncthreads();

        #pragma unroll
        for (int kc = 0; kc < 4; kc++) {
            uint32_t a0 = Xs[(wrow+qr  )*GP + kc*8 + qc];
            uint32_t a1 = Xs[(wrow+qr+8)*GP + kc*8 + qc];
            uint32_t a2 = Xs[(wrow+qr  )*GP + kc*8 + qc + 4];
            uint32_t a3 = Xs[(wrow+qr+8)*GP + kc*8 + qc + 4];
            #pragma unroll
            for (int j = 0; j < 8; j++) {
                uint32_t b0 = Ws[(j*8+qr)*GP + kc*8 + qc];
                uint32_t b1 = Ws[(j*8+qr)*GP + kc*8 + qc + 4];
                mma8(c[j], a0, a1, a2, a3, b0, b1);
            }
        }
    }

    const int row0 = m0 + wrow + qr;
    const int row1 = row0 + 8;
    #pragma unroll
    for (int j = 0; j < 8; j++) {
        int col = n0 + j*8 + qc*2;
        float b0 = bias[col], b1 = bias[col+1];
        float v00 = c[j][0] + b0, v01 = c[j][1] + b1;
        float v10 = c[j][2] + b0, v11 = c[j][3] + b1;
        if (headsplit) {
            int h = col >> 6, d = col & 63;
            {
                int bi = row0 >> 11, l = row0 & 2047;
                float* p = Y + (((size_t)(bi*NHEAD + h))*LL + l)*DHEAD + d;
                p[0] = v00; p[1] = v01;
            }
            {
                int bi = row1 >> 11, l = row1 & 2047;
                float* p = Y + (((size_t)(bi*NHEAD + h))*LL + l)*DHEAD + d;
                p[0] = v10; p[1] = v11;
            }
        } else {
            *(float2*)(Y + (size_t)row0*DMODEL + col) = make_float2(v00, v01);
            *(float2*)(Y + (size_t)row1*DMODEL + col) = make_float2(v10, v11);
        }
    }
}

// ---------------------------------------------------------------------------
// Fused attention (flash-style), TF32 tensor cores.
// BM=BN=64, 128 threads (4 warps), warp owns 16 query rows.
// Softmax state in registers (replicated across quads).
// coef folded into V at tile load; coef==0 doubles as pad mask.
// ---------------------------------------------------------------------------
#define KP 68   // K/P pitch: (4n + k) % 32 distinct for (n=lane>>2, k=lane&3) frags
#define VP 72   // V pitch:   (8k + d) % 32 distinct for (k=lane&3, d=lane>>2) frags
#define ATTN_SMEM ((64*KP + 64*VP + 64*KP + 64) * 4)

__global__ void __launch_bounds__(128) attn_kernel()
{
    extern __shared__ uint32_t smu[];
    uint32_t* Ks  = smu;              // [64][KP] tf32 K (also stages Q at start)
    uint32_t* Vs  = Ks + 64*KP;       // [64][VP] tf32 V*coef
    uint32_t* Ps  = Vs + 64*VP;       // [64][KP] tf32 P
    float*    kok = (float*)(Ps + 64*KP);  // [64]

    const int tid  = threadIdx.x;
    const int warp = tid >> 5, lane = tid & 31;
    const int qr = lane >> 2, qc = lane & 3;
    const int bh = blockIdx.y, bi = bh >> 3, h = bh & 7;
    const int q0 = blockIdx.x * 64;
    const int wrow = warp * 16;

    // ---- Stage Q (scaled by 1/8) through Ks, grab A-fragments ----
    const float* qbase = g_q + ((size_t)bh * LL + q0) * DHEAD;
    for (int idx = tid; idx < 64*16; idx += 128) {
        int r = idx >> 4, c4 = (idx & 15) << 2;
        float4 t = *(const float4*)(qbase + r*64 + c4);
        uint4 b = make_uint4(f2tf(t.x*0.125f), f2tf(t.y*0.125f),
                             f2tf(t.z*0.125f), f2tf(t.w*0.125f));
        *(uint4*)(Ks + r*KP + c4) = b;
    }
    __syncthreads();
    uint32_t aQ[8][4];
    #pragma unroll
    for (int kk = 0; kk < 8; kk++) {
        aQ[kk][0] = Ks[(wrow+qr  )*KP + kk*8 + qc];
        aQ[kk][1] = Ks[(wrow+qr+8)*KP + kk*8 + qc];
        aQ[kk][2] = Ks[(wrow+qr  )*KP + kk*8 + qc + 4];
        aQ[kk][3] = Ks[(wrow+qr+8)*KP + kk*8 + qc + 4];
    }
    const float qc0 = g_coef[bi*LL + q0 + wrow + qr];
    const float qc1 = g_coef[bi*LL + q0 + wrow + qr + 8];
    const bool q0ok = (qc0 != 0.0f), q1ok = (qc1 != 0.0f);

    float o[8][4] = {};
    float m0 = -1e30f, m1 = -1e30f, l0 = 0.0f, l1 = 0.0f;

    const float* kbase = g_k + (size_t)bh * LL * DHEAD;
    const float* vbase = g_v + (size_t)bh * LL * DHEAD;

    for (int k0 = 0; k0 < LL; k0 += 64) {
        __syncthreads();   // previous tile fully consumed (also covers Q staging read)
        for (int idx = tid; idx < 64*16; idx += 128) {
            int r = idx >> 4, c4 = (idx & 15) << 2;
            float cf = g_coef[bi*LL + k0 + r];
            float4 kt = *(const float4*)(kbase + (size_t)(k0 + r)*64 + c4);
            float4 vt = *(const float4*)(vbase + (size_t)(k0 + r)*64 + c4);
            *(uint4*)(Ks + r*KP + c4) =
                make_uint4(f2tf(kt.x), f2tf(kt.y), f2tf(kt.z), f2tf(kt.w));
            *(uint4*)(Vs + r*VP + c4) =
                make_uint4(f2tf(vt.x*cf), f2tf(vt.y*cf), f2tf(vt.z*cf), f2tf(vt.w*cf));
            if (c4 == 0) kok[r] = cf;
        }
        __syncthreads();

        // ---- S = (Q/8) @ K^T   (per-warp 16x64, tensor cores) ----
        float s[8][4] = {};
        #pragma unroll
        for (int kk = 0; kk < 8; kk++) {
            #pragma unroll
            for (int j = 0; j < 8; j++) {
                uint32_t b0 = Ks[(j*8+qr)*KP + kk*8 + qc];
                uint32_t b1 = Ks[(j*8+qr)*KP + kk*8 + qc + 4];
                mma8(s[j], aQ[kk][0], aQ[kk][1], aQ[kk][2], aQ[kk][3], b0, b1);
            }
        }

        // ---- mask ----
        #pragma unroll
        for (int j = 0; j < 8; j++) {
            bool kc0 = (kok[j*8 + qc*2    ] != 0.0f);
            bool kc1 = (kok[j*8 + qc*2 + 1] != 0.0f);
            if (!(q0ok && kc0)) s[j][0] = -10000.0f;
            if (!(q0ok && kc1)) s[j][1] = -10000.0f;
            if (!(q1ok && kc0)) s[j][2] = -10000.0f;
            if (!(q1ok && kc1)) s[j][3] = -10000.0f;
        }

        // ---- online softmax (state in regs, replicated across quad) ----
        float mx0 = -1e30f, mx1 = -1e30f;
        #pragma unroll
        for (int j = 0; j < 8; j++) {
            mx0 = fmaxf(mx0, fmaxf(s[j][0], s[j][1]));
            mx1 = fmaxf(mx1, fmaxf(s[j][2], s[j][3]));
        }
        mx0 = fmaxf(mx0, __shfl_xor_sync(0xffffffffu, mx0, 1));
        mx0 = fmaxf(mx0, __shfl_xor_sync(0xffffffffu, mx0, 2));
        mx1 = fmaxf(mx1, __shfl_xor_sync(0xffffffffu, mx1, 1));
        mx1 = fmaxf(mx1, __shfl_xor_sync(0xffffffffu, mx1, 2));
        float nm0 = fmaxf(m0, mx0), nm1 = fmaxf(m1, mx1);
        float sc0 = __expf(m0 - nm0), sc1 = __expf(m1 - nm1);
        m0 = nm0; m1 = nm1;

        float rs0 = 0.0f, rs1 = 0.0f;
        #pragma unroll
        for (int j = 0; j < 8; j++) {
            float p0 = __expf(s[j][0] - nm0);
            float p1 = __expf(s[j][1] - nm0);
            float p2 = __expf(s[j][2] - nm1);
            float p3 = __expf(s[j][3] - nm1);
            rs0 += p0 + p1; rs1 += p2 + p3;
            int col = j*8 + qc*2;
            *(uint2*)(Ps + (wrow+qr  )*KP + col) = make_uint2(f2tf(p0), f2tf(p1));
            *(uint2*)(Ps + (wrow+qr+8)*KP + col) = make_uint2(f2tf(p2), f2tf(p3));
        }
        rs0 += __shfl_xor_sync(0xffffffffu, rs0, 1);
        rs0 += __shfl_xor_sync(0xffffffffu, rs0, 2);
        rs1 += __shfl_xor_sync(0xffffffffu, rs1, 1);
        rs1 += __shfl_xor_sync(0xffffffffu, rs1, 2);
        l0 = l0*sc0 + rs0;
        l1 = l1*sc1 + rs1;

        #pragma unroll
        for (int j = 0; j < 8; j++) {
            o[j][0] *= sc0; o[j][1] *= sc0;
            o[j][2] *= sc1; o[j][3] *= sc1;
        }
        __syncwarp();   // each warp's P rows are private; warp-level fence suffices

        // ---- O += P @ (V*coef) ----
        #pragma unroll
        for (int kk = 0; kk < 8; kk++) {
            uint32_t a0 = Ps[(wrow+qr  )*KP + kk*8 + qc];
            uint32_t a1 = Ps[(wrow+qr+8)*KP + kk*8 + qc];
            uint32_t a2 = Ps[(wrow+qr  )*KP + kk*8 + qc + 4];
            uint32_t a3 = Ps[(wrow+qr+8)*KP + kk*8 + qc + 4];
            #pragma unroll
            for (int j = 0; j < 8; j++) {
                uint32_t b0 = Vs[(kk*8+qc  )*VP + j*8 + qr];
                uint32_t b1 = Vs[(kk*8+qc+4)*VP + j*8 + qr];
                mma8(o[j], a0, a1, a2, a3, b0, b1);
            }
        }
    }

    // ---- epilogue: normalize + write [B,L,H*Dh] ----
    float inv0 = 1.0f / l0, inv1 = 1.0f / l1;
    int r0 = q0 + wrow + qr, r1 = r0 + 8;
    #pragma unroll
    for (int j = 0; j < 8; j++) {
        int d = h*64 + j*8 + qc*2;
        *(float2*)(g_attn + ((size_t)(bi*LL + r0))*DMODEL + d) =
            make_float2(o[j][0]*inv0, o[j][1]*inv0);
        *(float2*)(g_attn + ((size_t)(bi*LL + r1))*DMODEL + d) =
            make_float2(o[j][2]*inv1, o[j][3]*inv1);
    }
}

// ---------------------------------------------------------------------------
extern "C" void kernel_launch(void* const* d_in, const int* in_sizes, int n_in,
                              void* d_out, int out_size)
{
    const float* q  = (const float*)d_in[0];
    const float* k  = (const float*)d_in[1];
    const float* v  = (const float*)d_in[2];
    const float* tm = (const float*)d_in[3];
    const float* am = (const float*)d_in[4];
    // d_in[5] = n_head (unused; hardcoded)
    const float* wq = (const float*)d_in[6];
    const float* bq = (const float*)d_in[7];
    const float* wk = (const float*)d_in[8];
    const float* bk = (const float*)d_in[9];
    const float* wv = (const float*)d_in[10];
    const float* bv = (const float*)d_in[11];
    const float* wo = (const float*)d_in[12];
    const float* bo = (const float*)d_in[13];
    float* out = (float*)d_out;

    float *gq, *gk, *gv, *gattn;
    cudaGetSymbolAddress((void**)&gq,    g_q);
    cudaGetSymbolAddress((void**)&gk,    g_k);
    cudaGetSymbolAddress((void**)&gv,    g_v);
    cudaGetSymbolAddress((void**)&gattn, g_attn);

    cudaFuncSetAttribute(attn_kernel, cudaFuncAttributeMaxDynamicSharedMemorySize, ATTN_SMEM);

    coef_kernel<<<2, 1024>>>(tm, am);
    dim3 gg(8, 64);
    sgemm_tc<<<gg, 128>>>(q, wq, bq, gq, 1);
    sgemm_tc<<<gg, 128>>>(k, wk, bk, gk, 1);
    sgemm_tc<<<gg, 128>>>(v, wv, bv, gv, 1);
    attn_kernel<<<dim3(32, 16), 128, ATTN_SMEM>>>();
    sgemm_tc<<<gg, 128>>>(gattn, wo, bo, out, 0);
}

// round 3
// speedup vs baseline: 3.3748x; 1.3092x over previous
#include <cuda_runtime.h>
#include <cstdint>

#define BB     2
#define LL     2048
#define LTXT   1024
#define DMODEL 512
#define NHEAD  8
#define DHEAD  64

// Scratch (device globals; no allocations allowed)
__device__ float g_q[BB*NHEAD*LL*DHEAD];
__device__ float g_k[BB*NHEAD*LL*DHEAD];
__device__ float g_v[BB*NHEAD*LL*DHEAD];
__device__ float g_attn[BB*LL*DMODEL];
__device__ float g_coef[BB*LL];

// ---------------------------------------------------------------------------
// Helpers
// ---------------------------------------------------------------------------
__device__ __forceinline__ uint32_t f2tf(float x) {
    uint32_t r;
    asm("cvt.rna.tf32.f32 %0, %1;" : "=r"(r) : "f"(x));
    return r;
}
__device__ __forceinline__ void mma8(float* c,
    uint32_t a0, uint32_t a1, uint32_t a2, uint32_t a3,
    uint32_t b0, uint32_t b1)
{
    asm("mma.sync.aligned.m16n8k8.row.col.f32.tf32.tf32.f32 "
        "{%0,%1,%2,%3},{%4,%5,%6,%7},{%8,%9},{%0,%1,%2,%3};"
        : "+f"(c[0]), "+f"(c[1]), "+f"(c[2]), "+f"(c[3])
        : "r"(a0), "r"(a1), "r"(a2), "r"(a3), "r"(b0), "r"(b1));
}
__device__ __forceinline__ void cp_async16(uint32_t saddr, const void* gptr) {
    asm volatile("cp.async.cg.shared.global [%0], [%1], 16;" :: "r"(saddr), "l"(gptr));
}

// ---------------------------------------------------------------------------
// Mask -> per-position post-softmax coefficient. coef==0 iff position masked.
// ---------------------------------------------------------------------------
__global__ void coef_kernel(const float* __restrict__ tm, const float* __restrict__ am)
{
    int b = blockIdx.x;
    int t = threadIdx.x;              // 1024 threads
    float tv = tm[b*LTXT + t];
    float av = am[b*LTXT + t];
    float ts = tv, as_ = av;
    #pragma unroll
    for (int o = 16; o; o >>= 1) {
        ts  += __shfl_xor_sync(0xffffffffu, ts,  o);
        as_ += __shfl_xor_sync(0xffffffffu, as_, o);
    }
    __shared__ float st[32], sa[32];
    int warp = t >> 5, lane = t & 31;
    if (lane == 0) { st[warp] = ts; sa[warp] = as_; }
    __syncthreads();
    if (warp == 0) {
        ts = st[lane]; as_ = sa[lane];
        #pragma unroll
        for (int o = 16; o; o >>= 1) {
            ts  += __shfl_xor_sync(0xffffffffu, ts,  o);
            as_ += __shfl_xor_sync(0xffffffffu, as_, o);
        }
        if (lane == 0) { st[0] = ts; sa[0] = as_; }
    }
    __syncthreads();
    float tsum = st[0], asum = sa[0], tot = tsum + asum;
    g_coef[b*LL + t]        = tv * (tot / (2.0f * tsum));
    g_coef[b*LL + LTXT + t] = av * (tot / (2.0f * asum));
}

// ---------------------------------------------------------------------------
// TF32 TC GEMM: Y = X @ W^T + bias.  M=4096, N=512, K=512.
// Block tile 128x64, 256 threads (8 warps in 4x2), warp tile 32x32.
// Double-buffered cp.async pipeline, BK=32.  blockIdx.z selects problem.
// headsplit=1: Y written as [B,H,L,Dh].
// ---------------------------------------------------------------------------
#define GP 36
#define XT (128*GP)
#define WT (64*GP)
#define GEMM_SMEM ((2*(XT + WT)) * 4)

struct GemmArgs {
    const float* X[3];
    const float* W[3];
    const float* bias[3];
    float*       Y[3];
    int headsplit;
};

__global__ void __launch_bounds__(256) gemm_tc(GemmArgs args)
{
    extern __shared__ float smf[];
    float* sX = smf;               // [2][128][GP]
    float* sW = smf + 2*XT;        // [2][64][GP]

    const int z = blockIdx.z;
    const float* __restrict__ X = args.X[z];
    const float* __restrict__ W = args.W[z];
    const float* __restrict__ B = args.bias[z];
    float* __restrict__ Y = args.Y[z];

    const int tid  = threadIdx.x;
    const int warp = tid >> 5, lane = tid & 31;
    const int qr = lane >> 2, qc = lane & 3;
    const int wm = (warp >> 1) * 32;   // warp row offset in 128
    const int wn = (warp & 1) * 32;    // warp col offset in 64
    const int m0 = blockIdx.y * 128, n0 = blockIdx.x * 64;

    // loader indices (raw f32 via cp.async; tf32 conversion at consume time)
    const int xr[4] = { (tid+  0)>>3, (tid+256)>>3, (tid+512)>>3, (tid+768)>>3 };
    const int xc    = (tid & 7) << 2;
    const int wr[2] = { (tid+  0)>>3, (tid+256)>>3 };

    auto load_tile = [&](int buf, int k0) {
        uint32_t bx = (uint32_t)__cvta_generic_to_shared(sX + buf*XT);
        uint32_t bw = (uint32_t)__cvta_generic_to_shared(sW + buf*WT);
        #pragma unroll
        for (int i = 0; i < 4; i++)
            cp_async16(bx + (xr[i]*GP + xc)*4, X + (size_t)(m0 + xr[i])*DMODEL + k0 + xc);
        #pragma unroll
        for (int i = 0; i < 2; i++)
            cp_async16(bw + (wr[i]*GP + xc)*4, W + (size_t)(n0 + wr[i])*DMODEL + k0 + xc);
        asm volatile("cp.async.commit_group;");
    };

    float c[2][4][4] = {};

    load_tile(0, 0);
    #pragma unroll 1
    for (int kc = 0; kc < DMODEL/32; kc++) {
        asm volatile("cp.async.wait_group 0;");
        __syncthreads();
        if (kc + 1 < DMODEL/32) load_tile((kc+1) & 1, (kc+1)*32);

        const float* Xb = sX + (kc & 1)*XT;
        const float* Wb = sW + (kc & 1)*WT;
        #pragma unroll
        for (int k8 = 0; k8 < 4; k8++) {
            uint32_t a[2][4];
            #pragma unroll
            for (int mi = 0; mi < 2; mi++) {
                int r = wm + mi*16 + qr;
                a[mi][0] = f2tf(Xb[(r  )*GP + k8*8 + qc]);
                a[mi][1] = f2tf(Xb[(r+8)*GP + k8*8 + qc]);
                a[mi][2] = f2tf(Xb[(r  )*GP + k8*8 + qc + 4]);
                a[mi][3] = f2tf(Xb[(r+8)*GP + k8*8 + qc + 4]);
            }
            #pragma unroll
            for (int nj = 0; nj < 4; nj++) {
                int r = wn + nj*8 + qr;
                uint32_t b0 = f2tf(Wb[r*GP + k8*8 + qc]);
                uint32_t b1 = f2tf(Wb[r*GP + k8*8 + qc + 4]);
                mma8(c[0][nj], a[0][0], a[0][1], a[0][2], a[0][3], b0, b1);
                mma8(c[1][nj], a[1][0], a[1][1], a[1][2], a[1][3], b0, b1);
            }
        }
        __syncthreads();
    }

    #pragma unroll
    for (int mi = 0; mi < 2; mi++) {
        int row0 = m0 + wm + mi*16 + qr;
        int row1 = row0 + 8;
        #pragma unroll
        for (int nj = 0; nj < 4; nj++) {
            int col = n0 + wn + nj*8 + qc*2;
            float b0 = B[col], b1 = B[col+1];
            float v00 = c[mi][nj][0] + b0, v01 = c[mi][nj][1] + b1;
            float v10 = c[mi][nj][2] + b0, v11 = c[mi][nj][3] + b1;
            if (args.headsplit) {
                int h = col >> 6, d = col & 63;
                {
                    int bi = row0 >> 11, l = row0 & 2047;
                    float* p = Y + (((size_t)(bi*NHEAD + h))*LL + l)*DHEAD + d;
                    p[0] = v00; p[1] = v01;
                }
                {
                    int bi = row1 >> 11, l = row1 & 2047;
                    float* p = Y + (((size_t)(bi*NHEAD + h))*LL + l)*DHEAD + d;
                    p[0] = v10; p[1] = v11;
                }
            } else {
                *(float2*)(Y + (size_t)row0*DMODEL + col) = make_float2(v00, v01);
                *(float2*)(Y + (size_t)row1*DMODEL + col) = make_float2(v10, v11);
            }
        }
    }
}

// ---------------------------------------------------------------------------
// Fused attention (flash-style), TF32 tensor cores.  (unchanged from R2)
// ---------------------------------------------------------------------------
#define KP 68
#define VP 72
#define ATTN_SMEM ((64*KP + 64*VP + 64*KP + 64) * 4)

__global__ void __launch_bounds__(128) attn_kernel()
{
    extern __shared__ uint32_t smu[];
    uint32_t* Ks  = smu;
    uint32_t* Vs  = Ks + 64*KP;
    uint32_t* Ps  = Vs + 64*VP;
    float*    kok = (float*)(Ps + 64*KP);

    const int tid  = threadIdx.x;
    const int warp = tid >> 5, lane = tid & 31;
    const int qr = lane >> 2, qc = lane & 3;
    const int bh = blockIdx.y, bi = bh >> 3, h = bh & 7;
    const int q0 = blockIdx.x * 64;
    const int wrow = warp * 16;

    const float* qbase = g_q + ((size_t)bh * LL + q0) * DHEAD;
    for (int idx = tid; idx < 64*16; idx += 128) {
        int r = idx >> 4, c4 = (idx & 15) << 2;
        float4 t = *(const float4*)(qbase + r*64 + c4);
        uint4 b = make_uint4(f2tf(t.x*0.125f), f2tf(t.y*0.125f),
                             f2tf(t.z*0.125f), f2tf(t.w*0.125f));
        *(uint4*)(Ks + r*KP + c4) = b;
    }
    __syncthreads();
    uint32_t aQ[8][4];
    #pragma unroll
    for (int kk = 0; kk < 8; kk++) {
        aQ[kk][0] = Ks[(wrow+qr  )*KP + kk*8 + qc];
        aQ[kk][1] = Ks[(wrow+qr+8)*KP + kk*8 + qc];
        aQ[kk][2] = Ks[(wrow+qr  )*KP + kk*8 + qc + 4];
        aQ[kk][3] = Ks[(wrow+qr+8)*KP + kk*8 + qc + 4];
    }
    const float qc0 = g_coef[bi*LL + q0 + wrow + qr];
    const float qc1 = g_coef[bi*LL + q0 + wrow + qr + 8];
    const bool q0ok = (qc0 != 0.0f), q1ok = (qc1 != 0.0f);

    float o[8][4] = {};
    float m0 = -1e30f, m1 = -1e30f, l0 = 0.0f, l1 = 0.0f;

    const float* kbase = g_k + (size_t)bh * LL * DHEAD;
    const float* vbase = g_v + (size_t)bh * LL * DHEAD;

    for (int k0 = 0; k0 < LL; k0 += 64) {
        __syncthreads();
        for (int idx = tid; idx < 64*16; idx += 128) {
            int r = idx >> 4, c4 = (idx & 15) << 2;
            float cf = g_coef[bi*LL + k0 + r];
            float4 kt = *(const float4*)(kbase + (size_t)(k0 + r)*64 + c4);
            float4 vt = *(const float4*)(vbase + (size_t)(k0 + r)*64 + c4);
            *(uint4*)(Ks + r*KP + c4) =
                make_uint4(f2tf(kt.x), f2tf(kt.y), f2tf(kt.z), f2tf(kt.w));
            *(uint4*)(Vs + r*VP + c4) =
                make_uint4(f2tf(vt.x*cf), f2tf(vt.y*cf), f2tf(vt.z*cf), f2tf(vt.w*cf));
            if (c4 == 0) kok[r] = cf;
        }
        __syncthreads();

        float s[8][4] = {};
        #pragma unroll
        for (int kk = 0; kk < 8; kk++) {
            #pragma unroll
            for (int j = 0; j < 8; j++) {
                uint32_t b0 = Ks[(j*8+qr)*KP + kk*8 + qc];
                uint32_t b1 = Ks[(j*8+qr)*KP + kk*8 + qc + 4];
                mma8(s[j], aQ[kk][0], aQ[kk][1], aQ[kk][2], aQ[kk][3], b0, b1);
            }
        }

        #pragma unroll
        for (int j = 0; j < 8; j++) {
            bool kc0 = (kok[j*8 + qc*2    ] != 0.0f);
            bool kc1 = (kok[j*8 + qc*2 + 1] != 0.0f);
            if (!(q0ok && kc0)) s[j][0] = -10000.0f;
            if (!(q0ok && kc1)) s[j][1] = -10000.0f;
            if (!(q1ok && kc0)) s[j][2] = -10000.0f;
            if (!(q1ok && kc1)) s[j][3] = -10000.0f;
        }

        float mx0 = -1e30f, mx1 = -1e30f;
        #pragma unroll
        for (int j = 0; j < 8; j++) {
            mx0 = fmaxf(mx0, fmaxf(s[j][0], s[j][1]));
            mx1 = fmaxf(mx1, fmaxf(s[j][2], s[j][3]));
        }
        mx0 = fmaxf(mx0, __shfl_xor_sync(0xffffffffu, mx0, 1));
        mx0 = fmaxf(mx0, __shfl_xor_sync(0xffffffffu, mx0, 2));
        mx1 = fmaxf(mx1, __shfl_xor_sync(0xffffffffu, mx1, 1));
        mx1 = fmaxf(mx1, __shfl_xor_sync(0xffffffffu, mx1, 2));
        float nm0 = fmaxf(m0, mx0), nm1 = fmaxf(m1, mx1);
        float sc0 = __expf(m0 - nm0), sc1 = __expf(m1 - nm1);
        m0 = nm0; m1 = nm1;

        float rs0 = 0.0f, rs1 = 0.0f;
        #pragma unroll
        for (int j = 0; j < 8; j++) {
            float p0 = __expf(s[j][0] - nm0);
            float p1 = __expf(s[j][1] - nm0);
            float p2 = __expf(s[j][2] - nm1);
            float p3 = __expf(s[j][3] - nm1);
            rs0 += p0 + p1; rs1 += p2 + p3;
            int col = j*8 + qc*2;
            *(uint2*)(Ps + (wrow+qr  )*KP + col) = make_uint2(f2tf(p0), f2tf(p1));
            *(uint2*)(Ps + (wrow+qr+8)*KP + col) = make_uint2(f2tf(p2), f2tf(p3));
        }
        rs0 += __shfl_xor_sync(0xffffffffu, rs0, 1);
        rs0 += __shfl_xor_sync(0xffffffffu, rs0, 2);
        rs1 += __shfl_xor_sync(0xffffffffu, rs1, 1);
        rs1 += __shfl_xor_sync(0xffffffffu, rs1, 2);
        l0 = l0*sc0 + rs0;
        l1 = l1*sc1 + rs1;

        #pragma unroll
        for (int j = 0; j < 8; j++) {
            o[j][0] *= sc0; o[j][1] *= sc0;
            o[j][2] *= sc1; o[j][3] *= sc1;
        }
        __syncwarp();

        #pragma unroll
        for (int kk = 0; kk < 8; kk++) {
            uint32_t a0 = Ps[(wrow+qr  )*KP + kk*8 + qc];
            uint32_t a1 = Ps[(wrow+qr+8)*KP + kk*8 + qc];
            uint32_t a2 = Ps[(wrow+qr  )*KP + kk*8 + qc + 4];
            uint32_t a3 = Ps[(wrow+qr+8)*KP + kk*8 + qc + 4];
            #pragma unroll
            for (int j = 0; j < 8; j++) {
                uint32_t b0 = Vs[(kk*8+qc  )*VP + j*8 + qr];
                uint32_t b1 = Vs[(kk*8+qc+4)*VP + j*8 + qr];
                mma8(o[j], a0, a1, a2, a3, b0, b1);
            }
        }
    }

    float inv0 = 1.0f / l0, inv1 = 1.0f / l1;
    int r0 = q0 + wrow + qr, r1 = r0 + 8;
    #pragma unroll
    for (int j = 0; j < 8; j++) {
        int d = h*64 + j*8 + qc*2;
        *(float2*)(g_attn + ((size_t)(bi*LL + r0))*DMODEL + d) =
            make_float2(o[j][0]*inv0, o[j][1]*inv0);
        *(float2*)(g_attn + ((size_t)(bi*LL + r1))*DMODEL + d) =
            make_float2(o[j][2]*inv1, o[j][3]*inv1);
    }
}

// ---------------------------------------------------------------------------
extern "C" void kernel_launch(void* const* d_in, const int* in_sizes, int n_in,
                              void* d_out, int out_size)
{
    const float* q  = (const float*)d_in[0];
    const float* k  = (const float*)d_in[1];
    const float* v  = (const float*)d_in[2];
    const float* tm = (const float*)d_in[3];
    const float* am = (const float*)d_in[4];
    const float* wq = (const float*)d_in[6];
    const float* bq = (const float*)d_in[7];
    const float* wk = (const float*)d_in[8];
    const float* bk = (const float*)d_in[9];
    const float* wv = (const float*)d_in[10];
    const float* bv = (const float*)d_in[11];
    const float* wo = (const float*)d_in[12];
    const float* bo = (const float*)d_in[13];
    float* out = (float*)d_out;

    float *gq, *gk, *gv, *gattn;
    cudaGetSymbolAddress((void**)&gq,    g_q);
    cudaGetSymbolAddress((void**)&gk,    g_k);
    cudaGetSymbolAddress((void**)&gv,    g_v);
    cudaGetSymbolAddress((void**)&gattn, g_attn);

    cudaFuncSetAttribute(gemm_tc, cudaFuncAttributeMaxDynamicSharedMemorySize, GEMM_SMEM);
    cudaFuncSetAttribute(attn_kernel, cudaFuncAttributeMaxDynamicSharedMemorySize, ATTN_SMEM);

    coef_kernel<<<2, 1024>>>(tm, am);

    GemmArgs qkv;
    qkv.X[0] = q;  qkv.X[1] = k;  qkv.X[2] = v;
    qkv.W[0] = wq; qkv.W[1] = wk; qkv.W[2] = wv;
    qkv.bias[0] = bq; qkv.bias[1] = bk; qkv.bias[2] = bv;
    qkv.Y[0] = gq; qkv.Y[1] = gk; qkv.Y[2] = gv;
    qkv.headsplit = 1;
    gemm_tc<<<dim3(8, 32, 3), 256, GEMM_SMEM>>>(qkv);

    attn_kernel<<<dim3(32, 16), 128, ATTN_SMEM>>>();

    GemmArgs og;
    og.X[0] = og.X[1] = og.X[2] = gattn;
    og.W[0] = og.W[1] = og.W[2] = wo;
    og.bias[0] = og.bias[1] = og.bias[2] = bo;
    og.Y[0] = og.Y[1] = og.Y[2] = out;
    og.headsplit = 0;
    gemm_tc<<<dim3(8, 32, 1), 256, GEMM_SMEM>>>(og);
}

// round 4
// speedup vs baseline: 3.9021x; 1.1562x over previous
#include <cuda_runtime.h>
#include <cstdint>

#define BB     2
#define LL     2048
#define LTXT   1024
#define DMODEL 512
#define NHEAD  8
#define DHEAD  64

// Scratch (device globals; no allocations allowed)
__device__ float g_q[BB*NHEAD*LL*DHEAD];
__device__ float g_k[BB*NHEAD*LL*DHEAD];
__device__ float g_v[BB*NHEAD*LL*DHEAD];
__device__ float g_attn[BB*LL*DMODEL];
__device__ float g_coef[BB*LL];

// ---------------------------------------------------------------------------
// Helpers
// ---------------------------------------------------------------------------
__device__ __forceinline__ uint32_t f2tf(float x) {
    uint32_t r;
    asm("cvt.rna.tf32.f32 %0, %1;" : "=r"(r) : "f"(x));
    return r;
}
__device__ __forceinline__ void mma8(float* c,
    uint32_t a0, uint32_t a1, uint32_t a2, uint32_t a3,
    uint32_t b0, uint32_t b1)
{
    asm("mma.sync.aligned.m16n8k8.row.col.f32.tf32.tf32.f32 "
        "{%0,%1,%2,%3},{%4,%5,%6,%7},{%8,%9},{%0,%1,%2,%3};"
        : "+f"(c[0]), "+f"(c[1]), "+f"(c[2]), "+f"(c[3])
        : "r"(a0), "r"(a1), "r"(a2), "r"(a3), "r"(b0), "r"(b1));
}
__device__ __forceinline__ void cp_async16(uint32_t saddr, const void* gptr) {
    asm volatile("cp.async.cg.shared.global [%0], [%1], 16;" :: "r"(saddr), "l"(gptr));
}

// ---------------------------------------------------------------------------
// Mask -> per-position post-softmax coefficient. coef==0 iff position masked.
// ---------------------------------------------------------------------------
__global__ void coef_kernel(const float* __restrict__ tm, const float* __restrict__ am)
{
    int b = blockIdx.x;
    int t = threadIdx.x;              // 1024 threads
    float tv = tm[b*LTXT + t];
    float av = am[b*LTXT + t];
    float ts = tv, as_ = av;
    #pragma unroll
    for (int o = 16; o; o >>= 1) {
        ts  += __shfl_xor_sync(0xffffffffu, ts,  o);
        as_ += __shfl_xor_sync(0xffffffffu, as_, o);
    }
    __shared__ float st[32], sa[32];
    int warp = t >> 5, lane = t & 31;
    if (lane == 0) { st[warp] = ts; sa[warp] = as_; }
    __syncthreads();
    if (warp == 0) {
        ts = st[lane]; as_ = sa[lane];
        #pragma unroll
        for (int o = 16; o; o >>= 1) {
            ts  += __shfl_xor_sync(0xffffffffu, ts,  o);
            as_ += __shfl_xor_sync(0xffffffffu, as_, o);
        }
        if (lane == 0) { st[0] = ts; sa[0] = as_; }
    }
    __syncthreads();
    float tsum = st[0], asum = sa[0], tot = tsum + asum;
    g_coef[b*LL + t]        = tv * (tot / (2.0f * tsum));
    g_coef[b*LL + LTXT + t] = av * (tot / (2.0f * asum));
}

// ---------------------------------------------------------------------------
// TF32 TC GEMM: Y = X @ W^T + bias.  M=4096, N=512, K=512. (unchanged R3)
// ---------------------------------------------------------------------------
#define GP 36
#define XT (128*GP)
#define WT (64*GP)
#define GEMM_SMEM ((2*(XT + WT)) * 4)

struct GemmArgs {
    const float* X[3];
    const float* W[3];
    const float* bias[3];
    float*       Y[3];
    int headsplit;
};

__global__ void __launch_bounds__(256) gemm_tc(GemmArgs args)
{
    extern __shared__ float smf[];
    float* sX = smf;
    float* sW = smf + 2*XT;

    const int z = blockIdx.z;
    const float* __restrict__ X = args.X[z];
    const float* __restrict__ W = args.W[z];
    const float* __restrict__ B = args.bias[z];
    float* __restrict__ Y = args.Y[z];

    const int tid  = threadIdx.x;
    const int warp = tid >> 5, lane = tid & 31;
    const int qr = lane >> 2, qc = lane & 3;
    const int wm = (warp >> 1) * 32;
    const int wn = (warp & 1) * 32;
    const int m0 = blockIdx.y * 128, n0 = blockIdx.x * 64;

    const int xr[4] = { (tid+  0)>>3, (tid+256)>>3, (tid+512)>>3, (tid+768)>>3 };
    const int xc    = (tid & 7) << 2;
    const int wr[2] = { (tid+  0)>>3, (tid+256)>>3 };

    auto load_tile = [&](int buf, int k0) {
        uint32_t bx = (uint32_t)__cvta_generic_to_shared(sX + buf*XT);
        uint32_t bw = (uint32_t)__cvta_generic_to_shared(sW + buf*WT);
        #pragma unroll
        for (int i = 0; i < 4; i++)
            cp_async16(bx + (xr[i]*GP + xc)*4, X + (size_t)(m0 + xr[i])*DMODEL + k0 + xc);
        #pragma unroll
        for (int i = 0; i < 2; i++)
            cp_async16(bw + (wr[i]*GP + xc)*4, W + (size_t)(n0 + wr[i])*DMODEL + k0 + xc);
        asm volatile("cp.async.commit_group;");
    };

    float c[2][4][4] = {};

    load_tile(0, 0);
    #pragma unroll 1
    for (int kc = 0; kc < DMODEL/32; kc++) {
        asm volatile("cp.async.wait_group 0;");
        __syncthreads();
        if (kc + 1 < DMODEL/32) load_tile((kc+1) & 1, (kc+1)*32);

        const float* Xb = sX + (kc & 1)*XT;
        const float* Wb = sW + (kc & 1)*WT;
        #pragma unroll
        for (int k8 = 0; k8 < 4; k8++) {
            uint32_t a[2][4];
            #pragma unroll
            for (int mi = 0; mi < 2; mi++) {
                int r = wm + mi*16 + qr;
                a[mi][0] = f2tf(Xb[(r  )*GP + k8*8 + qc]);
                a[mi][1] = f2tf(Xb[(r+8)*GP + k8*8 + qc]);
                a[mi][2] = f2tf(Xb[(r  )*GP + k8*8 + qc + 4]);
                a[mi][3] = f2tf(Xb[(r+8)*GP + k8*8 + qc + 4]);
            }
            #pragma unroll
            for (int nj = 0; nj < 4; nj++) {
                int r = wn + nj*8 + qr;
                uint32_t b0 = f2tf(Wb[r*GP + k8*8 + qc]);
                uint32_t b1 = f2tf(Wb[r*GP + k8*8 + qc + 4]);
                mma8(c[0][nj], a[0][0], a[0][1], a[0][2], a[0][3], b0, b1);
                mma8(c[1][nj], a[1][0], a[1][1], a[1][2], a[1][3], b0, b1);
            }
        }
        __syncthreads();
    }

    #pragma unroll
    for (int mi = 0; mi < 2; mi++) {
        int row0 = m0 + wm + mi*16 + qr;
        int row1 = row0 + 8;
        #pragma unroll
        for (int nj = 0; nj < 4; nj++) {
            int col = n0 + wn + nj*8 + qc*2;
            float b0 = B[col], b1 = B[col+1];
            float v00 = c[mi][nj][0] + b0, v01 = c[mi][nj][1] + b1;
            float v10 = c[mi][nj][2] + b0, v11 = c[mi][nj][3] + b1;
            if (args.headsplit) {
                int h = col >> 6, d = col & 63;
                {
                    int bi = row0 >> 11, l = row0 & 2047;
                    float* p = Y + (((size_t)(bi*NHEAD + h))*LL + l)*DHEAD + d;
                    p[0] = v00; p[1] = v01;
                }
                {
                    int bi = row1 >> 11, l = row1 & 2047;
                    float* p = Y + (((size_t)(bi*NHEAD + h))*LL + l)*DHEAD + d;
                    p[0] = v10; p[1] = v11;
                }
            } else {
                *(float2*)(Y + (size_t)row0*DMODEL + col) = make_float2(v00, v01);
                *(float2*)(Y + (size_t)row1*DMODEL + col) = make_float2(v10, v11);
            }
        }
    }
}

// ---------------------------------------------------------------------------
// Fused attention, TF32 tensor cores.  BM=128, BN=64, 256 threads (8 warps).
// Register-prefetch pipeline: next K/V tile LDG'd into regs during compute.
// ---------------------------------------------------------------------------
#define KP 68
#define VP 72
#define ATTN_SMEM ((64*KP + 64*VP + 128*KP + 64) * 4)

__global__ void __launch_bounds__(256) attn_kernel()
{
    extern __shared__ uint32_t smu[];
    uint32_t* Ks  = smu;                   // [64][KP] tf32 K
    uint32_t* Vs  = Ks + 64*KP;            // [64][VP] tf32 V*coef
    uint32_t* Ps  = Vs + 64*VP;            // [128][KP] tf32 P (stages Q first)
    float*    kok = (float*)(Ps + 128*KP); // [64]

    const int tid  = threadIdx.x;
    const int warp = tid >> 5, lane = tid & 31;
    const int qr = lane >> 2, qc = lane & 3;
    const int bh = blockIdx.y, bi = bh >> 3, h = bh & 7;
    const int q0 = blockIdx.x * 128;
    const int wrow = warp * 16;

    const float* kbase = g_k + (size_t)bh * LL * DHEAD;
    const float* vbase = g_v + (size_t)bh * LL * DHEAD;
    const float* cbase = g_coef + bi*LL;

    // loader slots: 64 rows x 16 float4-cols = 1024 slots / 256 threads = 4 each
    int lr[4], lc[4];
    #pragma unroll
    for (int i = 0; i < 4; i++) {
        int s = tid + i*256;
        lr[i] = s >> 4;
        lc[i] = (s & 15) << 2;
    }

    // ---- prefetch tile 0 into registers ----
    float4 kreg[4], vreg[4];
    float  creg[4];
    #pragma unroll
    for (int i = 0; i < 4; i++) {
        kreg[i] = *(const float4*)(kbase + (size_t)lr[i]*64 + lc[i]);
        vreg[i] = *(const float4*)(vbase + (size_t)lr[i]*64 + lc[i]);
        creg[i] = __ldg(cbase + lr[i]);
    }

    // ---- stage Q (scaled by 1/8) through Ps, grab A-fragments ----
    const float* qbase = g_q + ((size_t)bh * LL + q0) * DHEAD;
    for (int idx = tid; idx < 128*16; idx += 256) {
        int r = idx >> 4, c4 = (idx & 15) << 2;
        float4 t = *(const float4*)(qbase + r*64 + c4);
        uint4 b = make_uint4(f2tf(t.x*0.125f), f2tf(t.y*0.125f),
                             f2tf(t.z*0.125f), f2tf(t.w*0.125f));
        *(uint4*)(Ps + r*KP + c4) = b;
    }
    __syncthreads();
    uint32_t aQ[8][4];
    #pragma unroll
    for (int kk = 0; kk < 8; kk++) {
        aQ[kk][0] = Ps[(wrow+qr  )*KP + kk*8 + qc];
        aQ[kk][1] = Ps[(wrow+qr+8)*KP + kk*8 + qc];
        aQ[kk][2] = Ps[(wrow+qr  )*KP + kk*8 + qc + 4];
        aQ[kk][3] = Ps[(wrow+qr+8)*KP + kk*8 + qc + 4];
    }
    const bool q0ok = (cbase[q0 + wrow + qr]     != 0.0f);
    const bool q1ok = (cbase[q0 + wrow + qr + 8] != 0.0f);

    float o[8][4] = {};
    float m0 = -1e30f, m1 = -1e30f, l0 = 0.0f, l1 = 0.0f;

    #pragma unroll 1
    for (int k0 = 0; k0 < LL; k0 += 64) {
        __syncthreads();   // all warps done reading smem (prev tile / Q frags)
        // ---- commit prefetched tile to smem (tf32; V pre-scaled by coef) ----
        #pragma unroll
        for (int i = 0; i < 4; i++) {
            float cf = creg[i];
            *(uint4*)(Ks + lr[i]*KP + lc[i]) =
                make_uint4(f2tf(kreg[i].x), f2tf(kreg[i].y), f2tf(kreg[i].z), f2tf(kreg[i].w));
            *(uint4*)(Vs + lr[i]*VP + lc[i]) =
                make_uint4(f2tf(vreg[i].x*cf), f2tf(vreg[i].y*cf),
                           f2tf(vreg[i].z*cf), f2tf(vreg[i].w*cf));
            if (lc[i] == 0) kok[lr[i]] = cf;
        }
        __syncthreads();

        // ---- issue next tile's loads (consumed next iteration) ----
        if (k0 + 64 < LL) {
            #pragma unroll
            for (int i = 0; i < 4; i++) {
                kreg[i] = *(const float4*)(kbase + (size_t)(k0+64 + lr[i])*64 + lc[i]);
                vreg[i] = *(const float4*)(vbase + (size_t)(k0+64 + lr[i])*64 + lc[i]);
                creg[i] = __ldg(cbase + k0+64 + lr[i]);
            }
        }

        // ---- S = (Q/8) @ K^T ----
        float s[8][4] = {};
        #pragma unroll
        for (int kk = 0; kk < 8; kk++) {
            #pragma unroll
            for (int j = 0; j < 8; j++) {
                uint32_t b0 = Ks[(j*8+qr)*KP + kk*8 + qc];
                uint32_t b1 = Ks[(j*8+qr)*KP + kk*8 + qc + 4];
                mma8(s[j], aQ[kk][0], aQ[kk][1], aQ[kk][2], aQ[kk][3], b0, b1);
            }
        }

        // ---- mask ----
        #pragma unroll
        for (int j = 0; j < 8; j++) {
            bool kc0 = (kok[j*8 + qc*2    ] != 0.0f);
            bool kc1 = (kok[j*8 + qc*2 + 1] != 0.0f);
            if (!(q0ok && kc0)) s[j][0] = -10000.0f;
            if (!(q0ok && kc1)) s[j][1] = -10000.0f;
            if (!(q1ok && kc0)) s[j][2] = -10000.0f;
            if (!(q1ok && kc1)) s[j][3] = -10000.0f;
        }

        // ---- online softmax ----
        float mx0 = -1e30f, mx1 = -1e30f;
        #pragma unroll
        for (int j = 0; j < 8; j++) {
            mx0 = fmaxf(mx0, fmaxf(s[j][0], s[j][1]));
            mx1 = fmaxf(mx1, fmaxf(s[j][2], s[j][3]));
        }
        mx0 = fmaxf(mx0, __shfl_xor_sync(0xffffffffu, mx0, 1));
        mx0 = fmaxf(mx0, __shfl_xor_sync(0xffffffffu, mx0, 2));
        mx1 = fmaxf(mx1, __shfl_xor_sync(0xffffffffu, mx1, 1));
        mx1 = fmaxf(mx1, __shfl_xor_sync(0xffffffffu, mx1, 2));
        float nm0 = fmaxf(m0, mx0), nm1 = fmaxf(m1, mx1);
        float sc0 = __expf(m0 - nm0), sc1 = __expf(m1 - nm1);
        m0 = nm0; m1 = nm1;

        float rs0 = 0.0f, rs1 = 0.0f;
        #pragma unroll
        for (int j = 0; j < 8; j++) {
            float p0 = __expf(s[j][0] - nm0);
            float p1 = __expf(s[j][1] - nm0);
            float p2 = __expf(s[j][2] - nm1);
            float p3 = __expf(s[j][3] - nm1);
            rs0 += p0 + p1; rs1 += p2 + p3;
            int col = j*8 + qc*2;
            *(uint2*)(Ps + (wrow+qr  )*KP + col) = make_uint2(f2tf(p0), f2tf(p1));
            *(uint2*)(Ps + (wrow+qr+8)*KP + col) = make_uint2(f2tf(p2), f2tf(p3));
        }
        rs0 += __shfl_xor_sync(0xffffffffu, rs0, 1);
        rs0 += __shfl_xor_sync(0xffffffffu, rs0, 2);
        rs1 += __shfl_xor_sync(0xffffffffu, rs1, 1);
        rs1 += __shfl_xor_sync(0xffffffffu, rs1, 2);
        l0 = l0*sc0 + rs0;
        l1 = l1*sc1 + rs1;

        #pragma unroll
        for (int j = 0; j < 8; j++) {
            o[j][0] *= sc0; o[j][1] *= sc0;
            o[j][2] *= sc1; o[j][3] *= sc1;
        }
        __syncwarp();   // each warp's P rows are private

        // ---- O += P @ (V*coef) ----
        #pragma unroll
        for (int kk = 0; kk < 8; kk++) {
            uint32_t a0 = Ps[(wrow+qr  )*KP + kk*8 + qc];
            uint32_t a1 = Ps[(wrow+qr+8)*KP + kk*8 + qc];
            uint32_t a2 = Ps[(wrow+qr  )*KP + kk*8 + qc + 4];
            uint32_t a3 = Ps[(wrow+qr+8)*KP + kk*8 + qc + 4];
            #pragma unroll
            for (int j = 0; j < 8; j++) {
                uint32_t b0 = Vs[(kk*8+qc  )*VP + j*8 + qr];
                uint32_t b1 = Vs[(kk*8+qc+4)*VP + j*8 + qr];
                mma8(o[j], a0, a1, a2, a3, b0, b1);
            }
        }
    }

    // ---- epilogue ----
    float inv0 = 1.0f / l0, inv1 = 1.0f / l1;
    int r0 = q0 + wrow + qr, r1 = r0 + 8;
    #pragma unroll
    for (int j = 0; j < 8; j++) {
        int d = h*64 + j*8 + qc*2;
        *(float2*)(g_attn + ((size_t)(bi*LL + r0))*DMODEL + d) =
            make_float2(o[j][0]*inv0, o[j][1]*inv0);
        *(float2*)(g_attn + ((size_t)(bi*LL + r1))*DMODEL + d) =
            make_float2(o[j][2]*inv1, o[j][3]*inv1);
    }
}

// ---------------------------------------------------------------------------
extern "C" void kernel_launch(void* const* d_in, const int* in_sizes, int n_in,
                              void* d_out, int out_size)
{
    const float* q  = (const float*)d_in[0];
    const float* k  = (const float*)d_in[1];
    const float* v  = (const float*)d_in[2];
    const float* tm = (const float*)d_in[3];
    const float* am = (const float*)d_in[4];
    const float* wq = (const float*)d_in[6];
    const float* bq = (const float*)d_in[7];
    const float* wk = (const float*)d_in[8];
    const float* bk = (const float*)d_in[9];
    const float* wv = (const float*)d_in[10];
    const float* bv = (const float*)d_in[11];
    const float* wo = (const float*)d_in[12];
    const float* bo = (const float*)d_in[13];
    float* out = (float*)d_out;

    float *gq, *gk, *gv, *gattn;
    cudaGetSymbolAddress((void**)&gq,    g_q);
    cudaGetSymbolAddress((void**)&gk,    g_k);
    cudaGetSymbolAddress((void**)&gv,    g_v);
    cudaGetSymbolAddress((void**)&gattn, g_attn);

    cudaFuncSetAttribute(gemm_tc, cudaFuncAttributeMaxDynamicSharedMemorySize, GEMM_SMEM);
    cudaFuncSetAttribute(attn_kernel, cudaFuncAttributeMaxDynamicSharedMemorySize, ATTN_SMEM);

    coef_kernel<<<2, 1024>>>(tm, am);

    GemmArgs qkv;
    qkv.X[0] = q;  qkv.X[1] = k;  qkv.X[2] = v;
    qkv.W[0] = wq; qkv.W[1] = wk; qkv.W[2] = wv;
    qkv.bias[0] = bq; qkv.bias[1] = bk; qkv.bias[2] = bv;
    qkv.Y[0] = gq; qkv.Y[1] = gk; qkv.Y[2] = gv;
    qkv.headsplit = 1;
    gemm_tc<<<dim3(8, 32, 3), 256, GEMM_SMEM>>>(qkv);

    attn_kernel<<<dim3(16, 16), 256, ATTN_SMEM>>>();

    GemmArgs og;
    og.X[0] = og.X[1] = og.X[2] = gattn;
    og.W[0] = og.W[1] = og.W[2] = wo;
    og.bias[0] = og.bias[1] = og.bias[2] = bo;
    og.Y[0] = og.Y[1] = og.Y[2] = out;
    og.headsplit = 0;
    gemm_tc<<<dim3(8, 32, 1), 256, GEMM_SMEM>>>(og);
}

// round 5
// speedup vs baseline: 4.1659x; 1.0676x over previous
#include <cuda_runtime.h>
#include <cstdint>

#define BB     2
#define LL     2048
#define LTXT   1024
#define DMODEL 512
#define NHEAD  8
#define DHEAD  64

// Scratch (device globals; no allocations allowed)
__device__ float g_q[BB*NHEAD*LL*DHEAD];     // pre-scaled (1/8) + tf32-rounded
__device__ float g_k[BB*NHEAD*LL*DHEAD];     // tf32-rounded
__device__ float g_v[BB*NHEAD*LL*DHEAD];     // pre-multiplied by coef + tf32-rounded
__device__ float g_attn[BB*LL*DMODEL];
__device__ float g_coef[BB*LL];

// ---------------------------------------------------------------------------
// Helpers
// ---------------------------------------------------------------------------
__device__ __forceinline__ uint32_t f2tf(float x) {
    uint32_t r;
    asm("cvt.rna.tf32.f32 %0, %1;" : "=r"(r) : "f"(x));
    return r;
}
__device__ __forceinline__ void mma8(float* c,
    uint32_t a0, uint32_t a1, uint32_t a2, uint32_t a3,
    uint32_t b0, uint32_t b1)
{
    asm("mma.sync.aligned.m16n8k8.row.col.f32.tf32.tf32.f32 "
        "{%0,%1,%2,%3},{%4,%5,%6,%7},{%8,%9},{%0,%1,%2,%3};"
        : "+f"(c[0]), "+f"(c[1]), "+f"(c[2]), "+f"(c[3])
        : "r"(a0), "r"(a1), "r"(a2), "r"(a3), "r"(b0), "r"(b1));
}
__device__ __forceinline__ void cp_async16(uint32_t saddr, const void* gptr) {
    asm volatile("cp.async.cg.shared.global [%0], [%1], 16;" :: "r"(saddr), "l"(gptr));
}

// ---------------------------------------------------------------------------
// Mask -> per-position post-softmax coefficient. coef==0 iff position masked.
// ---------------------------------------------------------------------------
__global__ void coef_kernel(const float* __restrict__ tm, const float* __restrict__ am)
{
    int b = blockIdx.x;
    int t = threadIdx.x;              // 1024 threads
    float tv = tm[b*LTXT + t];
    float av = am[b*LTXT + t];
    float ts = tv, as_ = av;
    #pragma unroll
    for (int o = 16; o; o >>= 1) {
        ts  += __shfl_xor_sync(0xffffffffu, ts,  o);
        as_ += __shfl_xor_sync(0xffffffffu, as_, o);
    }
    __shared__ float st[32], sa[32];
    int warp = t >> 5, lane = t & 31;
    if (lane == 0) { st[warp] = ts; sa[warp] = as_; }
    __syncthreads();
    if (warp == 0) {
        ts = st[lane]; as_ = sa[lane];
        #pragma unroll
        for (int o = 16; o; o >>= 1) {
            ts  += __shfl_xor_sync(0xffffffffu, ts,  o);
            as_ += __shfl_xor_sync(0xffffffffu, as_, o);
        }
        if (lane == 0) { st[0] = ts; sa[0] = as_; }
    }
    __syncthreads();
    float tsum = st[0], asum = sa[0], tot = tsum + asum;
    g_coef[b*LL + t]        = tv * (tot / (2.0f * tsum));
    g_coef[b*LL + LTXT + t] = av * (tot / (2.0f * asum));
}

// ---------------------------------------------------------------------------
// TF32 TC GEMM v2: Y = X @ W^T + bias.  M=4096, N=512, K=512.
// Block 128x64, 256 threads (8 warps 4x2), warp 32x32.
// tf32 conversion ONCE at smem-store; inner loop is pure LDS+mma.
// Register-prefetch double buffer (LDG next chunk during compute).
// Epilogue modes per z: 0=plain f32, 1=Q(*0.125,round), 2=K(round), 3=V(*coef,round)
// ---------------------------------------------------------------------------
#define GP 36
#define XT (128*GP)
#define WT (64*GP)
#define GEMM_SMEM ((2*(XT + WT)) * 4)

struct GemmArgs {
    const float* X[3];
    const float* W[3];
    const float* bias[3];
    float*       Y[3];
    int          mode[3];
    const float* coef;
};

__global__ void __launch_bounds__(256) gemm_tc(GemmArgs args)
{
    extern __shared__ uint32_t smg[];
    uint32_t* sX = smg;               // [2][128][GP] tf32 bits
    uint32_t* sW = smg + 2*XT;        // [2][64][GP]

    const int z = blockIdx.z;
    const float* __restrict__ X = args.X[z];
    const float* __restrict__ W = args.W[z];
    const float* __restrict__ B = args.bias[z];
    float* __restrict__ Y = args.Y[z];
    const int mode = args.mode[z];

    const int tid  = threadIdx.x;
    const int warp = tid >> 5, lane = tid & 31;
    const int qr = lane >> 2, qc = lane & 3;
    const int wm = (warp >> 1) * 32;
    const int wn = (warp & 1) * 32;
    const int m0 = blockIdx.y * 128, n0 = blockIdx.x * 64;

    const int xr[4] = { (tid+  0)>>3, (tid+256)>>3, (tid+512)>>3, (tid+768)>>3 };
    const int xc    = (tid & 7) << 2;
    const int wr[2] = { (tid+  0)>>3, (tid+256)>>3 };

    float4 xbuf[4], wbuf[2];
    auto ldreg = [&](int k0) {
        #pragma unroll
        for (int i = 0; i < 4; i++)
            xbuf[i] = *(const float4*)(X + (size_t)(m0 + xr[i])*DMODEL + k0 + xc);
        #pragma unroll
        for (int i = 0; i < 2; i++)
            wbuf[i] = *(const float4*)(W + (size_t)(n0 + wr[i])*DMODEL + k0 + xc);
    };
    auto stsmem = [&](int buf) {
        #pragma unroll
        for (int i = 0; i < 4; i++)
            *(uint4*)(sX + buf*XT + xr[i]*GP + xc) =
                make_uint4(f2tf(xbuf[i].x), f2tf(xbuf[i].y), f2tf(xbuf[i].z), f2tf(xbuf[i].w));
        #pragma unroll
        for (int i = 0; i < 2; i++)
            *(uint4*)(sW + buf*WT + wr[i]*GP + xc) =
                make_uint4(f2tf(wbuf[i].x), f2tf(wbuf[i].y), f2tf(wbuf[i].z), f2tf(wbuf[i].w));
    };

    float c[2][4][4] = {};

    ldreg(0);
    #pragma unroll 1
    for (int kc = 0; kc < DMODEL/32; kc++) {
        stsmem(kc & 1);
        __syncthreads();
        if (kc + 1 < DMODEL/32) ldreg((kc+1)*32);

        const uint32_t* Xb = sX + (kc & 1)*XT;
        const uint32_t* Wb = sW + (kc & 1)*WT;
        #pragma unroll
        for (int k8 = 0; k8 < 4; k8++) {
            uint32_t a[2][4];
            #pragma unroll
            for (int mi = 0; mi < 2; mi++) {
                int r = wm + mi*16 + qr;
                a[mi][0] = Xb[(r  )*GP + k8*8 + qc];
                a[mi][1] = Xb[(r+8)*GP + k8*8 + qc];
                a[mi][2] = Xb[(r  )*GP + k8*8 + qc + 4];
                a[mi][3] = Xb[(r+8)*GP + k8*8 + qc + 4];
            }
            #pragma unroll
            for (int nj = 0; nj < 4; nj++) {
                int r = wn + nj*8 + qr;
                uint32_t b0 = Wb[r*GP + k8*8 + qc];
                uint32_t b1 = Wb[r*GP + k8*8 + qc + 4];
                mma8(c[0][nj], a[0][0], a[0][1], a[0][2], a[0][3], b0, b1);
                mma8(c[1][nj], a[1][0], a[1][1], a[1][2], a[1][3], b0, b1);
            }
        }
        __syncthreads();
    }

    #pragma unroll
    for (int mi = 0; mi < 2; mi++) {
        int row0 = m0 + wm + mi*16 + qr;
        int row1 = row0 + 8;
        #pragma unroll
        for (int nj = 0; nj < 4; nj++) {
            int col = n0 + wn + nj*8 + qc*2;
            float b0 = B[col], b1 = B[col+1];
            float v00 = c[mi][nj][0] + b0, v01 = c[mi][nj][1] + b1;
            float v10 = c[mi][nj][2] + b0, v11 = c[mi][nj][3] + b1;
            if (mode == 0) {
                *(float2*)(Y + (size_t)row0*DMODEL + col) = make_float2(v00, v01);
                *(float2*)(Y + (size_t)row1*DMODEL + col) = make_float2(v10, v11);
            } else {
                if (mode == 1) {            // Q: scale + round
                    v00 *= 0.125f; v01 *= 0.125f; v10 *= 0.125f; v11 *= 0.125f;
                } else if (mode == 3) {     // V: coef + round
                    float c0 = args.coef[row0], c1 = args.coef[row1];
                    v00 *= c0; v01 *= c0; v10 *= c1; v11 *= c1;
                }
                uint2 u0 = make_uint2(f2tf(v00), f2tf(v01));
                uint2 u1 = make_uint2(f2tf(v10), f2tf(v11));
                int h = col >> 6, d = col & 63;
                {
                    int bi = row0 >> 11, l = row0 & 2047;
                    *(uint2*)((uint32_t*)Y + (((size_t)(bi*NHEAD + h))*LL + l)*DHEAD + d) = u0;
                }
                {
                    int bi = row1 >> 11, l = row1 & 2047;
                    *(uint2*)((uint32_t*)Y + (((size_t)(bi*NHEAD + h))*LL + l)*DHEAD + d) = u1;
                }
            }
        }
    }
}

// ---------------------------------------------------------------------------
// Fused attention v3.  BM=128, BN=64, 256 threads (8 warps).
// K/V/coef pre-converted by producer -> loader is cp.async byte copy,
// double-buffered smem, zero math in the load path.
// ---------------------------------------------------------------------------
#define KP 68
#define VP 72
#define KS_T (64*KP)
#define VS_T (64*VP)
#define ATTN_SMEM ((2*KS_T + 2*VS_T + 2*64 + 128*KP) * 4)

__global__ void __launch_bounds__(256) attn_kernel()
{
    extern __shared__ uint32_t smu[];
    uint32_t* Ks  = smu;                       // [2][64][KP]
    uint32_t* Vs  = smu + 2*KS_T;              // [2][64][VP]
    float*    kok = (float*)(smu + 2*KS_T + 2*VS_T);  // [2][64]
    uint32_t* Ps  = smu + 2*KS_T + 2*VS_T + 2*64;     // [128][KP] (stages Q first)

    const int tid  = threadIdx.x;
    const int warp = tid >> 5, lane = tid & 31;
    const int qr = lane >> 2, qc = lane & 3;
    const int bh = blockIdx.y, bi = bh >> 3, h = bh & 7;
    const int q0 = blockIdx.x * 128;
    const int wrow = warp * 16;

    const float* kbase = g_k + (size_t)bh * LL * DHEAD;
    const float* vbase = g_v + (size_t)bh * LL * DHEAD;
    const float* cbase = g_coef + bi*LL;

    const uint32_t sK = (uint32_t)__cvta_generic_to_shared(Ks);
    const uint32_t sV = (uint32_t)__cvta_generic_to_shared(Vs);
    const uint32_t sC = (uint32_t)__cvta_generic_to_shared(kok);

    int lr[4], lc[4];
    #pragma unroll
    for (int i = 0; i < 4; i++) {
        int s = tid + i*256;
        lr[i] = s >> 4;
        lc[i] = (s & 15) << 2;
    }

    auto prefetch = [&](int buf, int k0) {
        #pragma unroll
        for (int i = 0; i < 4; i++) {
            cp_async16(sK + (buf*KS_T + lr[i]*KP + lc[i])*4,
                       kbase + (size_t)(k0 + lr[i])*64 + lc[i]);
            cp_async16(sV + (buf*VS_T + lr[i]*VP + lc[i])*4,
                       vbase + (size_t)(k0 + lr[i])*64 + lc[i]);
        }
        if (tid < 16)
            cp_async16(sC + (buf*64 + tid*4)*4, cbase + k0 + tid*4);
        asm volatile("cp.async.commit_group;");
    };

    // ---- prefetch tile 0 ----
    prefetch(0, 0);

    // ---- stage Q (already scaled+rounded) through Ps, grab A-fragments ----
    const float* qbase = g_q + ((size_t)bh * LL + q0) * DHEAD;
    for (int idx = tid; idx < 128*16; idx += 256) {
        int r = idx >> 4, c4 = (idx & 15) << 2;
        *(uint4*)(Ps + r*KP + c4) = *(const uint4*)(qbase + r*64 + c4);
    }
    __syncthreads();
    uint32_t aQ[8][4];
    #pragma unroll
    for (int kk = 0; kk < 8; kk++) {
        aQ[kk][0] = Ps[(wrow+qr  )*KP + kk*8 + qc];
        aQ[kk][1] = Ps[(wrow+qr+8)*KP + kk*8 + qc];
        aQ[kk][2] = Ps[(wrow+qr  )*KP + kk*8 + qc + 4];
        aQ[kk][3] = Ps[(wrow+qr+8)*KP + kk*8 + qc + 4];
    }
    const bool q0ok = (cbase[q0 + wrow + qr]     != 0.0f);
    const bool q1ok = (cbase[q0 + wrow + qr + 8] != 0.0f);

    float o[8][4] = {};
    float m0 = -1e30f, m1 = -1e30f, l0 = 0.0f, l1 = 0.0f;

    #pragma unroll 1
    for (int t = 0; t < LL/64; t++) {
        asm volatile("cp.async.wait_group 0;");
        __syncthreads();     // tile ready; prev compute done (incl. Q frag reads)
        if (t + 1 < LL/64) prefetch((t+1) & 1, (t+1)*64);

        const uint32_t* Kb = Ks + (t & 1)*KS_T;
        const uint32_t* Vb = Vs + (t & 1)*VS_T;
        const float*    kb = kok + (t & 1)*64;

        // ---- S = (Q/8) @ K^T ----
        float s[8][4] = {};
        #pragma unroll
        for (int kk = 0; kk < 8; kk++) {
            #pragma unroll
            for (int j = 0; j < 8; j++) {
                uint32_t b0 = Kb[(j*8+qr)*KP + kk*8 + qc];
                uint32_t b1 = Kb[(j*8+qr)*KP + kk*8 + qc + 4];
                mma8(s[j], aQ[kk][0], aQ[kk][1], aQ[kk][2], aQ[kk][3], b0, b1);
            }
        }

        // ---- mask ----
        #pragma unroll
        for (int j = 0; j < 8; j++) {
            bool kc0 = (kb[j*8 + qc*2    ] != 0.0f);
            bool kc1 = (kb[j*8 + qc*2 + 1] != 0.0f);
            if (!(q0ok && kc0)) s[j][0] = -10000.0f;
            if (!(q0ok && kc1)) s[j][1] = -10000.0f;
            if (!(q1ok && kc0)) s[j][2] = -10000.0f;
            if (!(q1ok && kc1)) s[j][3] = -10000.0f;
        }

        // ---- online softmax ----
        float mx0 = -1e30f, mx1 = -1e30f;
        #pragma unroll
        for (int j = 0; j < 8; j++) {
            mx0 = fmaxf(mx0, fmaxf(s[j][0], s[j][1]));
            mx1 = fmaxf(mx1, fmaxf(s[j][2], s[j][3]));
        }
        mx0 = fmaxf(mx0, __shfl_xor_sync(0xffffffffu, mx0, 1));
        mx0 = fmaxf(mx0, __shfl_xor_sync(0xffffffffu, mx0, 2));
        mx1 = fmaxf(mx1, __shfl_xor_sync(0xffffffffu, mx1, 1));
        mx1 = fmaxf(mx1, __shfl_xor_sync(0xffffffffu, mx1, 2));
        float nm0 = fmaxf(m0, mx0), nm1 = fmaxf(m1, mx1);
        float sc0 = __expf(m0 - nm0), sc1 = __expf(m1 - nm1);
        m0 = nm0; m1 = nm1;

        float rs0 = 0.0f, rs1 = 0.0f;
        #pragma unroll
        for (int j = 0; j < 8; j++) {
            float p0 = __expf(s[j][0] - nm0);
            float p1 = __expf(s[j][1] - nm0);
            float p2 = __expf(s[j][2] - nm1);
            float p3 = __expf(s[j][3] - nm1);
            rs0 += p0 + p1; rs1 += p2 + p3;
            int col = j*8 + qc*2;
            *(uint2*)(Ps + (wrow+qr  )*KP + col) = make_uint2(f2tf(p0), f2tf(p1));
            *(uint2*)(Ps + (wrow+qr+8)*KP + col) = make_uint2(f2tf(p2), f2tf(p3));
        }
        rs0 += __shfl_xor_sync(0xffffffffu, rs0, 1);
        rs0 += __shfl_xor_sync(0xffffffffu, rs0, 2);
        rs1 += __shfl_xor_sync(0xffffffffu, rs1, 1);
        rs1 += __shfl_xor_sync(0xffffffffu, rs1, 2);
        l0 = l0*sc0 + rs0;
        l1 = l1*sc1 + rs1;

        #pragma unroll
        for (int j = 0; j < 8; j++) {
            o[j][0] *= sc0; o[j][1] *= sc0;
            o[j][2] *= sc1; o[j][3] *= sc1;
        }
        __syncwarp();   // each warp's P rows are private

        // ---- O += P @ (V*coef) ----
        #pragma unroll
        for (int kk = 0; kk < 8; kk++) {
            uint32_t a0 = Ps[(wrow+qr  )*KP + kk*8 + qc];
            uint32_t a1 = Ps[(wrow+qr+8)*KP + kk*8 + qc];
            uint32_t a2 = Ps[(wrow+qr  )*KP + kk*8 + qc + 4];
            uint32_t a3 = Ps[(wrow+qr+8)*KP + kk*8 + qc + 4];
            #pragma unroll
            for (int j = 0; j < 8; j++) {
                uint32_t b0 = Vb[(kk*8+qc  )*VP + j*8 + qr];
                uint32_t b1 = Vb[(kk*8+qc+4)*VP + j*8 + qr];
                mma8(o[j], a0, a1, a2, a3, b0, b1);
            }
        }
    }

    // ---- epilogue ----
    float inv0 = 1.0f / l0, inv1 = 1.0f / l1;
    int r0 = q0 + wrow + qr, r1 = r0 + 8;
    #pragma unroll
    for (int j = 0; j < 8; j++) {
        int d = h*64 + j*8 + qc*2;
        *(float2*)(g_attn + ((size_t)(bi*LL + r0))*DMODEL + d) =
            make_float2(o[j][0]*inv0, o[j][1]*inv0);
        *(float2*)(g_attn + ((size_t)(bi*LL + r1))*DMODEL + d) =
            make_float2(o[j][2]*inv1, o[j][3]*inv1);
    }
}

// ---------------------------------------------------------------------------
extern "C" void kernel_launch(void* const* d_in, const int* in_sizes, int n_in,
                              void* d_out, int out_size)
{
    const float* q  = (const float*)d_in[0];
    const float* k  = (const float*)d_in[1];
    const float* v  = (const float*)d_in[2];
    const float* tm = (const float*)d_in[3];
    const float* am = (const float*)d_in[4];
    const float* wq = (const float*)d_in[6];
    const float* bq = (const float*)d_in[7];
    const float* wk = (const float*)d_in[8];
    const float* bk = (const float*)d_in[9];
    const float* wv = (const float*)d_in[10];
    const float* bv = (const float*)d_in[11];
    const float* wo = (const float*)d_in[12];
    const float* bo = (const float*)d_in[13];
    float* out = (float*)d_out;

    float *gq, *gk, *gv, *gattn, *gcoef;
    cudaGetSymbolAddress((void**)&gq,    g_q);
    cudaGetSymbolAddress((void**)&gk,    g_k);
    cudaGetSymbolAddress((void**)&gv,    g_v);
    cudaGetSymbolAddress((void**)&gattn, g_attn);
    cudaGetSymbolAddress((void**)&gcoef, g_coef);

    cudaFuncSetAttribute(gemm_tc, cudaFuncAttributeMaxDynamicSharedMemorySize, GEMM_SMEM);
    cudaFuncSetAttribute(attn_kernel, cudaFuncAttributeMaxDynamicSharedMemorySize, ATTN_SMEM);

    coef_kernel<<<2, 1024>>>(tm, am);   // must precede QKV (V epilogue reads coef)

    GemmArgs qkv;
    qkv.X[0] = q;  qkv.X[1] = k;  qkv.X[2] = v;
    qkv.W[0] = wq; qkv.W[1] = wk; qkv.W[2] = wv;
    qkv.bias[0] = bq; qkv.bias[1] = bk; qkv.bias[2] = bv;
    qkv.Y[0] = gq; qkv.Y[1] = gk; qkv.Y[2] = gv;
    qkv.mode[0] = 1; qkv.mode[1] = 2; qkv.mode[2] = 3;
    qkv.coef = gcoef;
    gemm_tc<<<dim3(8, 32, 3), 256, GEMM_SMEM>>>(qkv);

    attn_kernel<<<dim3(16, 16), 256, ATTN_SMEM>>>();

    GemmArgs og;
    og.X[0] = og.X[1] = og.X[2] = gattn;
    og.W[0] = og.W[1] = og.W[2] = wo;
    og.bias[0] = og.bias[1] = og.bias[2] = bo;
    og.Y[0] = og.Y[1] = og.Y[2] = out;
    og.mode[0] = og.mode[1] = og.mode[2] = 0;
    og.coef = gcoef;
    gemm_tc<<<dim3(8, 32, 1), 256, GEMM_SMEM>>>(og);
}

// round 6
// speedup vs baseline: 4.3621x; 1.0471x over previous
#include <cuda_runtime.h>
#include <cstdint>

#define BB     2
#define LL     2048
#define LTXT   1024
#define DMODEL 512
#define NHEAD  8
#define DHEAD  64

// Scratch (device globals; no allocations allowed)
__device__ float g_q[BB*NHEAD*LL*DHEAD];     // pre-scaled (1/8) + tf32-rounded
__device__ float g_k[BB*NHEAD*LL*DHEAD];     // tf32-rounded
__device__ float g_v[BB*NHEAD*LL*DHEAD];     // pre-multiplied by coef + tf32-rounded
__device__ float g_attn[BB*LL*DMODEL];
__device__ float g_coef[BB*LL];

// ---------------------------------------------------------------------------
// Helpers
// ---------------------------------------------------------------------------
__device__ __forceinline__ uint32_t f2tf(float x) {
    uint32_t r;
    asm("cvt.rna.tf32.f32 %0, %1;" : "=r"(r) : "f"(x));
    return r;
}
__device__ __forceinline__ void mma8(float* c,
    uint32_t a0, uint32_t a1, uint32_t a2, uint32_t a3,
    uint32_t b0, uint32_t b1)
{
    asm("mma.sync.aligned.m16n8k8.row.col.f32.tf32.tf32.f32 "
        "{%0,%1,%2,%3},{%4,%5,%6,%7},{%8,%9},{%0,%1,%2,%3};"
        : "+f"(c[0]), "+f"(c[1]), "+f"(c[2]), "+f"(c[3])
        : "r"(a0), "r"(a1), "r"(a2), "r"(a3), "r"(b0), "r"(b1));
}
__device__ __forceinline__ void cp_async16(uint32_t saddr, const void* gptr) {
    asm volatile("cp.async.cg.shared.global [%0], [%1], 16;" :: "r"(saddr), "l"(gptr));
}

// ---------------------------------------------------------------------------
// Mask -> per-position post-softmax coefficient. coef==0 iff position masked.
// ---------------------------------------------------------------------------
__global__ void coef_kernel(const float* __restrict__ tm, const float* __restrict__ am)
{
    int b = blockIdx.x;
    int t = threadIdx.x;              // 1024 threads
    float tv = tm[b*LTXT + t];
    float av = am[b*LTXT + t];
    float ts = tv, as_ = av;
    #pragma unroll
    for (int o = 16; o; o >>= 1) {
        ts  += __shfl_xor_sync(0xffffffffu, ts,  o);
        as_ += __shfl_xor_sync(0xffffffffu, as_, o);
    }
    __shared__ float st[32], sa[32];
    int warp = t >> 5, lane = t & 31;
    if (lane == 0) { st[warp] = ts; sa[warp] = as_; }
    __syncthreads();
    if (warp == 0) {
        ts = st[lane]; as_ = sa[lane];
        #pragma unroll
        for (int o = 16; o; o >>= 1) {
            ts  += __shfl_xor_sync(0xffffffffu, ts,  o);
            as_ += __shfl_xor_sync(0xffffffffu, as_, o);
        }
        if (lane == 0) { st[0] = ts; sa[0] = as_; }
    }
    __syncthreads();
    float tsum = st[0], asum = sa[0], tot = tsum + asum;
    g_coef[b*LL + t]        = tv * (tot / (2.0f * tsum));
    g_coef[b*LL + LTXT + t] = av * (tot / (2.0f * asum));
}

// ---------------------------------------------------------------------------
// TF32 TC GEMM v2 (unchanged from R5): Y = X @ W^T + bias.
// ---------------------------------------------------------------------------
#define GP 36
#define XT (128*GP)
#define WT (64*GP)
#define GEMM_SMEM ((2*(XT + WT)) * 4)

struct GemmArgs {
    const float* X[3];
    const float* W[3];
    const float* bias[3];
    float*       Y[3];
    int          mode[3];
    const float* coef;
};

__global__ void __launch_bounds__(256) gemm_tc(GemmArgs args)
{
    extern __shared__ uint32_t smg[];
    uint32_t* sX = smg;
    uint32_t* sW = smg + 2*XT;

    const int z = blockIdx.z;
    const float* __restrict__ X = args.X[z];
    const float* __restrict__ W = args.W[z];
    const float* __restrict__ B = args.bias[z];
    float* __restrict__ Y = args.Y[z];
    const int mode = args.mode[z];

    const int tid  = threadIdx.x;
    const int warp = tid >> 5, lane = tid & 31;
    const int qr = lane >> 2, qc = lane & 3;
    const int wm = (warp >> 1) * 32;
    const int wn = (warp & 1) * 32;
    const int m0 = blockIdx.y * 128, n0 = blockIdx.x * 64;

    const int xr[4] = { (tid+  0)>>3, (tid+256)>>3, (tid+512)>>3, (tid+768)>>3 };
    const int xc    = (tid & 7) << 2;
    const int wr[2] = { (tid+  0)>>3, (tid+256)>>3 };

    float4 xbuf[4], wbuf[2];
    auto ldreg = [&](int k0) {
        #pragma unroll
        for (int i = 0; i < 4; i++)
            xbuf[i] = *(const float4*)(X + (size_t)(m0 + xr[i])*DMODEL + k0 + xc);
        #pragma unroll
        for (int i = 0; i < 2; i++)
            wbuf[i] = *(const float4*)(W + (size_t)(n0 + wr[i])*DMODEL + k0 + xc);
    };
    auto stsmem = [&](int buf) {
        #pragma unroll
        for (int i = 0; i < 4; i++)
            *(uint4*)(sX + buf*XT + xr[i]*GP + xc) =
                make_uint4(f2tf(xbuf[i].x), f2tf(xbuf[i].y), f2tf(xbuf[i].z), f2tf(xbuf[i].w));
        #pragma unroll
        for (int i = 0; i < 2; i++)
            *(uint4*)(sW + buf*WT + wr[i]*GP + xc) =
                make_uint4(f2tf(wbuf[i].x), f2tf(wbuf[i].y), f2tf(wbuf[i].z), f2tf(wbuf[i].w));
    };

    float c[2][4][4] = {};

    ldreg(0);
    #pragma unroll 1
    for (int kc = 0; kc < DMODEL/32; kc++) {
        stsmem(kc & 1);
        __syncthreads();
        if (kc + 1 < DMODEL/32) ldreg((kc+1)*32);

        const uint32_t* Xb = sX + (kc & 1)*XT;
        const uint32_t* Wb = sW + (kc & 1)*WT;
        #pragma unroll
        for (int k8 = 0; k8 < 4; k8++) {
            uint32_t a[2][4];
            #pragma unroll
            for (int mi = 0; mi < 2; mi++) {
                int r = wm + mi*16 + qr;
                a[mi][0] = Xb[(r  )*GP + k8*8 + qc];
                a[mi][1] = Xb[(r+8)*GP + k8*8 + qc];
                a[mi][2] = Xb[(r  )*GP + k8*8 + qc + 4];
                a[mi][3] = Xb[(r+8)*GP + k8*8 + qc + 4];
            }
            #pragma unroll
            for (int nj = 0; nj < 4; nj++) {
                int r = wn + nj*8 + qr;
                uint32_t b0 = Wb[r*GP + k8*8 + qc];
                uint32_t b1 = Wb[r*GP + k8*8 + qc + 4];
                mma8(c[0][nj], a[0][0], a[0][1], a[0][2], a[0][3], b0, b1);
                mma8(c[1][nj], a[1][0], a[1][1], a[1][2], a[1][3], b0, b1);
            }
        }
        __syncthreads();
    }

    #pragma unroll
    for (int mi = 0; mi < 2; mi++) {
        int row0 = m0 + wm + mi*16 + qr;
        int row1 = row0 + 8;
        #pragma unroll
        for (int nj = 0; nj < 4; nj++) {
            int col = n0 + wn + nj*8 + qc*2;
            float b0 = B[col], b1 = B[col+1];
            float v00 = c[mi][nj][0] + b0, v01 = c[mi][nj][1] + b1;
            float v10 = c[mi][nj][2] + b0, v11 = c[mi][nj][3] + b1;
            if (mode == 0) {
                *(float2*)(Y + (size_t)row0*DMODEL + col) = make_float2(v00, v01);
                *(float2*)(Y + (size_t)row1*DMODEL + col) = make_float2(v10, v11);
            } else {
                if (mode == 1) {
                    v00 *= 0.125f; v01 *= 0.125f; v10 *= 0.125f; v11 *= 0.125f;
                } else if (mode == 3) {
                    float c0 = args.coef[row0], c1 = args.coef[row1];
                    v00 *= c0; v01 *= c0; v10 *= c1; v11 *= c1;
                }
                uint2 u0 = make_uint2(f2tf(v00), f2tf(v01));
                uint2 u1 = make_uint2(f2tf(v10), f2tf(v11));
                int h = col >> 6, d = col & 63;
                {
                    int bi = row0 >> 11, l = row0 & 2047;
                    *(uint2*)((uint32_t*)Y + (((size_t)(bi*NHEAD + h))*LL + l)*DHEAD + d) = u0;
                }
                {
                    int bi = row1 >> 11, l = row1 & 2047;
                    *(uint2*)((uint32_t*)Y + (((size_t)(bi*NHEAD + h))*LL + l)*DHEAD + d) = u1;
                }
            }
        }
    }
}

// ---------------------------------------------------------------------------
// Fused attention v4.  BM=128, BN=64, 256 threads (8 warps), 2 CTAs/SM.
// P never touches smem: S c-fragments are permuted into PV A-fragments with
// quad shuffles.  Q fragments LDG'd directly (producer pre-rounded).
// ---------------------------------------------------------------------------
#define KP 68
#define VP 72
#define KS_T (64*KP)
#define VS_T (64*VP)
#define ATTN_SMEM ((2*KS_T + 2*VS_T + 2*64) * 4)

__global__ void __launch_bounds__(256, 2) attn_kernel()
{
    extern __shared__ uint32_t smu[];
    uint32_t* Ks  = smu;                              // [2][64][KP]
    uint32_t* Vs  = smu + 2*KS_T;                     // [2][64][VP]
    float*    kok = (float*)(smu + 2*KS_T + 2*VS_T);  // [2][64]

    const int tid  = threadIdx.x;
    const int warp = tid >> 5, lane = tid & 31;
    const int qr = lane >> 2, qc = lane & 3;
    const int bh = blockIdx.y, bi = bh >> 3, h = bh & 7;
    const int q0 = blockIdx.x * 128;
    const int wrow = warp * 16;

    const float* kbase = g_k + (size_t)bh * LL * DHEAD;
    const float* vbase = g_v + (size_t)bh * LL * DHEAD;
    const float* cbase = g_coef + bi*LL;

    const uint32_t sK = (uint32_t)__cvta_generic_to_shared(Ks);
    const uint32_t sV = (uint32_t)__cvta_generic_to_shared(Vs);
    const uint32_t sC = (uint32_t)__cvta_generic_to_shared(kok);

    int lr[4], lc[4];
    #pragma unroll
    for (int i = 0; i < 4; i++) {
        int s = tid + i*256;
        lr[i] = s >> 4;
        lc[i] = (s & 15) << 2;
    }

    auto prefetch = [&](int buf, int k0) {
        #pragma unroll
        for (int i = 0; i < 4; i++) {
            cp_async16(sK + (buf*KS_T + lr[i]*KP + lc[i])*4,
                       kbase + (size_t)(k0 + lr[i])*64 + lc[i]);
            cp_async16(sV + (buf*VS_T + lr[i]*VP + lc[i])*4,
                       vbase + (size_t)(k0 + lr[i])*64 + lc[i]);
        }
        if (tid < 16)
            cp_async16(sC + (buf*64 + tid*4)*4, cbase + k0 + tid*4);
        asm volatile("cp.async.commit_group;");
    };

    prefetch(0, 0);

    // ---- Q fragments straight from gmem (bits already tf32-rounded, /8) ----
    const uint32_t* qrow0 =
        (const uint32_t*)(g_q + ((size_t)bh*LL + q0 + wrow + qr)*DHEAD);
    const uint32_t* qrow1 = qrow0 + 8*DHEAD;
    uint32_t aQ[8][4];
    #pragma unroll
    for (int kk = 0; kk < 8; kk++) {
        aQ[kk][0] = qrow0[kk*8 + qc];
        aQ[kk][1] = qrow1[kk*8 + qc];
        aQ[kk][2] = qrow0[kk*8 + qc + 4];
        aQ[kk][3] = qrow1[kk*8 + qc + 4];
    }
    const bool q0ok = (cbase[q0 + wrow + qr]     != 0.0f);
    const bool q1ok = (cbase[q0 + wrow + qr + 8] != 0.0f);

    // quad shuffle sources for c-frag -> a-frag permutation
    const int s0 = (lane & ~3) | (qc >> 1);
    const int s1 = s0 + 2;
    const bool odd = qc & 1;

    float o[8][4] = {};
    float m0 = -1e30f, m1 = -1e30f, l0 = 0.0f, l1 = 0.0f;

    #pragma unroll 1
    for (int t = 0; t < LL/64; t++) {
        asm volatile("cp.async.wait_group 0;");
        __syncthreads();
        if (t + 1 < LL/64) prefetch((t+1) & 1, (t+1)*64);

        const uint32_t* Kb = Ks + (t & 1)*KS_T;
        const uint32_t* Vb = Vs + (t & 1)*VS_T;
        const float*    kb = kok + (t & 1)*64;

        // ---- S = (Q/8) @ K^T ----
        float s[8][4] = {};
        #pragma unroll
        for (int kk = 0; kk < 8; kk++) {
            #pragma unroll
            for (int j = 0; j < 8; j++) {
                uint32_t b0 = Kb[(j*8+qr)*KP + kk*8 + qc];
                uint32_t b1 = Kb[(j*8+qr)*KP + kk*8 + qc + 4];
                mma8(s[j], aQ[kk][0], aQ[kk][1], aQ[kk][2], aQ[kk][3], b0, b1);
            }
        }

        // ---- mask ----
        #pragma unroll
        for (int j = 0; j < 8; j++) {
            bool kc0 = (kb[j*8 + qc*2    ] != 0.0f);
            bool kc1 = (kb[j*8 + qc*2 + 1] != 0.0f);
            if (!(q0ok && kc0)) s[j][0] = -10000.0f;
            if (!(q0ok && kc1)) s[j][1] = -10000.0f;
            if (!(q1ok && kc0)) s[j][2] = -10000.0f;
            if (!(q1ok && kc1)) s[j][3] = -10000.0f;
        }

        // ---- online softmax: row max ----
        float mx0 = -1e30f, mx1 = -1e30f;
        #pragma unroll
        for (int j = 0; j < 8; j++) {
            mx0 = fmaxf(mx0, fmaxf(s[j][0], s[j][1]));
            mx1 = fmaxf(mx1, fmaxf(s[j][2], s[j][3]));
        }
        mx0 = fmaxf(mx0, __shfl_xor_sync(0xffffffffu, mx0, 1));
        mx0 = fmaxf(mx0, __shfl_xor_sync(0xffffffffu, mx0, 2));
        mx1 = fmaxf(mx1, __shfl_xor_sync(0xffffffffu, mx1, 1));
        mx1 = fmaxf(mx1, __shfl_xor_sync(0xffffffffu, mx1, 2));
        float nm0 = fmaxf(m0, mx0), nm1 = fmaxf(m1, mx1);
        float sc0 = __expf(m0 - nm0), sc1 = __expf(m1 - nm1);
        m0 = nm0; m1 = nm1;

        #pragma unroll
        for (int j = 0; j < 8; j++) {
            o[j][0] *= sc0; o[j][1] *= sc0;
            o[j][2] *= sc1; o[j][3] *= sc1;
        }

        // ---- exp + shuffle-permute into PV A-fragments + PV mma ----
        float rs0 = 0.0f, rs1 = 0.0f;
        #pragma unroll
        for (int j = 0; j < 8; j++) {     // j is the K-chunk of PV (kk == j)
            float p0 = __expf(s[j][0] - nm0);
            float p1 = __expf(s[j][1] - nm0);
            float p2 = __expf(s[j][2] - nm1);
            float p3 = __expf(s[j][3] - nm1);
            rs0 += p0 + p1; rs1 += p2 + p3;

            float e00 = __shfl_sync(0xffffffffu, p0, s0);
            float e01 = __shfl_sync(0xffffffffu, p1, s0);
            float e10 = __shfl_sync(0xffffffffu, p0, s1);
            float e11 = __shfl_sync(0xffffffffu, p1, s1);
            float f00 = __shfl_sync(0xffffffffu, p2, s0);
            float f01 = __shfl_sync(0xffffffffu, p3, s0);
            float f10 = __shfl_sync(0xffffffffu, p2, s1);
            float f11 = __shfl_sync(0xffffffffu, p3, s1);
            uint32_t a0 = f2tf(odd ? e01 : e00);   // P[qr,   j*8+qc]
            uint32_t a1 = f2tf(odd ? f01 : f00);   // P[qr+8, j*8+qc]
            uint32_t a2 = f2tf(odd ? e11 : e10);   // P[qr,   j*8+qc+4]
            uint32_t a3 = f2tf(odd ? f11 : f10);   // P[qr+8, j*8+qc+4]

            #pragma unroll
            for (int nj = 0; nj < 8; nj++) {
                uint32_t b0 = Vb[(j*8+qc  )*VP + nj*8 + qr];
                uint32_t b1 = Vb[(j*8+qc+4)*VP + nj*8 + qr];
                mma8(o[nj], a0, a1, a2, a3, b0, b1);
            }
        }
        rs0 += __shfl_xor_sync(0xffffffffu, rs0, 1);
        rs0 += __shfl_xor_sync(0xffffffffu, rs0, 2);
        rs1 += __shfl_xor_sync(0xffffffffu, rs1, 1);
        rs1 += __shfl_xor_sync(0xffffffffu, rs1, 2);
        l0 = l0*sc0 + rs0;
        l1 = l1*sc1 + rs1;
    }

    // ---- epilogue ----
    float inv0 = 1.0f / l0, inv1 = 1.0f / l1;
    int r0 = q0 + wrow + qr, r1 = r0 + 8;
    #pragma unroll
    for (int j = 0; j < 8; j++) {
        int d = h*64 + j*8 + qc*2;
        *(float2*)(g_attn + ((size_t)(bi*LL + r0))*DMODEL + d) =
            make_float2(o[j][0]*inv0, o[j][1]*inv0);
        *(float2*)(g_attn + ((size_t)(bi*LL + r1))*DMODEL + d) =
            make_float2(o[j][2]*inv1, o[j][3]*inv1);
    }
}

// ---------------------------------------------------------------------------
extern "C" void kernel_launch(void* const* d_in, const int* in_sizes, int n_in,
                              void* d_out, int out_size)
{
    const float* q  = (const float*)d_in[0];
    const float* k  = (const float*)d_in[1];
    const float* v  = (const float*)d_in[2];
    const float* tm = (const float*)d_in[3];
    const float* am = (const float*)d_in[4];
    const float* wq = (const float*)d_in[6];
    const float* bq = (const float*)d_in[7];
    const float* wk = (const float*)d_in[8];
    const float* bk = (const float*)d_in[9];
    const float* wv = (const float*)d_in[10];
    const float* bv = (const float*)d_in[11];
    const float* wo = (const float*)d_in[12];
    const float* bo = (const float*)d_in[13];
    float* out = (float*)d_out;

    float *gq, *gk, *gv, *gattn, *gcoef;
    cudaGetSymbolAddress((void**)&gq,    g_q);
    cudaGetSymbolAddress((void**)&gk,    g_k);
    cudaGetSymbolAddress((void**)&gv,    g_v);
    cudaGetSymbolAddress((void**)&gattn, g_attn);
    cudaGetSymbolAddress((void**)&gcoef, g_coef);

    cudaFuncSetAttribute(gemm_tc, cudaFuncAttributeMaxDynamicSharedMemorySize, GEMM_SMEM);
    cudaFuncSetAttribute(attn_kernel, cudaFuncAttributeMaxDynamicSharedMemorySize, ATTN_SMEM);

    coef_kernel<<<2, 1024>>>(tm, am);   // must precede QKV (V epilogue reads coef)

    GemmArgs qkv;
    qkv.X[0] = q;  qkv.X[1] = k;  qkv.X[2] = v;
    qkv.W[0] = wq; qkv.W[1] = wk; qkv.W[2] = wv;
    qkv.bias[0] = bq; qkv.bias[1] = bk; qkv.bias[2] = bv;
    qkv.Y[0] = gq; qkv.Y[1] = gk; qkv.Y[2] = gv;
    qkv.mode[0] = 1; qkv.mode[1] = 2; qkv.mode[2] = 3;
    qkv.coef = gcoef;
    gemm_tc<<<dim3(8, 32, 3), 256, GEMM_SMEM>>>(qkv);

    attn_kernel<<<dim3(16, 16), 256, ATTN_SMEM>>>();

    GemmArgs og;
    og.X[0] = og.X[1] = og.X[2] = gattn;
    og.W[0] = og.W[1] = og.W[2] = wo;
    og.bias[0] = og.bias[1] = og.bias[2] = bo;
    og.Y[0] = og.Y[1] = og.Y[2] = out;
    og.mode[0] = og.mode[1] = og.mode[2] = 0;
    og.coef = gcoef;
    gemm_tc<<<dim3(8, 32, 1), 256, GEMM_SMEM>>>(og);
}

// round 7
// speedup vs baseline: 7.2441x; 1.6607x over previous
#include <cuda_runtime.h>
#include <cuda_fp16.h>
#include <cstdint>

#define BB     2
#define LL     2048
#define LTXT   1024
#define DMODEL 512
#define NHEAD  8
#define DHEAD  64

// Scratch (device globals; no allocations allowed)
__device__ __half g_qh[BB*NHEAD*LL*DHEAD];    // [bh][l][d], pre-scaled 1/8
__device__ __half g_kh[BB*NHEAD*LL*DHEAD];    // [bh][l][d]
__device__ __half g_vh[BB*NHEAD*LL*DHEAD];    // TRANSPOSED [bh][d][l], pre-mul coef
__device__ __half g_attnh[BB*LL*DMODEL];      // [l][512]
__device__ float  g_coef[BB*LL];

// ---------------------------------------------------------------------------
// Helpers
// ---------------------------------------------------------------------------
__device__ __forceinline__ uint32_t pk(float lo, float hi) {
    __half2 h = __floats2half2_rn(lo, hi);
    return *reinterpret_cast<uint32_t*>(&h);
}
__device__ __forceinline__ void mma16(float* c,
    uint32_t a0, uint32_t a1, uint32_t a2, uint32_t a3,
    uint32_t b0, uint32_t b1)
{
    asm("mma.sync.aligned.m16n8k16.row.col.f32.f16.f16.f32 "
        "{%0,%1,%2,%3},{%4,%5,%6,%7},{%8,%9},{%0,%1,%2,%3};"
        : "+f"(c[0]), "+f"(c[1]), "+f"(c[2]), "+f"(c[3])
        : "r"(a0), "r"(a1), "r"(a2), "r"(a3), "r"(b0), "r"(b1));
}
__device__ __forceinline__ void cp_async16(uint32_t saddr, const void* gptr) {
    asm volatile("cp.async.cg.shared.global [%0], [%1], 16;" :: "r"(saddr), "l"(gptr));
}

// ---------------------------------------------------------------------------
// Mask -> per-position post-softmax coefficient. coef==0 iff position masked.
// ---------------------------------------------------------------------------
__global__ void coef_kernel(const float* __restrict__ tm, const float* __restrict__ am)
{
    int b = blockIdx.x;
    int t = threadIdx.x;              // 1024 threads
    float tv = tm[b*LTXT + t];
    float av = am[b*LTXT + t];
    float ts = tv, as_ = av;
    #pragma unroll
    for (int o = 16; o; o >>= 1) {
        ts  += __shfl_xor_sync(0xffffffffu, ts,  o);
        as_ += __shfl_xor_sync(0xffffffffu, as_, o);
    }
    __shared__ float st[32], sa[32];
    int warp = t >> 5, lane = t & 31;
    if (lane == 0) { st[warp] = ts; sa[warp] = as_; }
    __syncthreads();
    if (warp == 0) {
        ts = st[lane]; as_ = sa[lane];
        #pragma unroll
        for (int o = 16; o; o >>= 1) {
            ts  += __shfl_xor_sync(0xffffffffu, ts,  o);
            as_ += __shfl_xor_sync(0xffffffffu, as_, o);
        }
        if (lane == 0) { st[0] = ts; sa[0] = as_; }
    }
    __syncthreads();
    float tsum = st[0], asum = sa[0], tot = tsum + asum;
    g_coef[b*LL + t]        = tv * (tot / (2.0f * tsum));
    g_coef[b*LL + LTXT + t] = av * (tot / (2.0f * asum));
}

// ---------------------------------------------------------------------------
// FP16 TC GEMM (QKV): Y = X @ W^T + bias.  f32 inputs -> fp16 outputs.
// Block 128x64, 256 threads (8 warps 4x2), warp 32x32, BK=32, m16n8k16.
// mode 1: Q (*0.125, [bh][l][d]); 2: K ([bh][l][d]); 3: V (*coef, TRANSPOSED [bh][d][l])
// ---------------------------------------------------------------------------
#define GKP 20   // smem pitch in words (32 halves = 16 words + 4 pad; 80B = 16B-mult)

struct QkvArgs {
    const float* X[3];
    const float* W[3];
    const float* bias[3];
    __half*      Y[3];
    int          mode[3];
    const float* coef;
};

__global__ void __launch_bounds__(256) gemm_qkv(QkvArgs args)
{
    __shared__ uint32_t sX[2][128*GKP];
    __shared__ uint32_t sW[2][64*GKP];

    const int z = blockIdx.z;
    const float* __restrict__ X = args.X[z];
    const float* __restrict__ W = args.W[z];
    const float* __restrict__ B = args.bias[z];
    __half* __restrict__ Y = args.Y[z];
    const int mode = args.mode[z];

    const int tid  = threadIdx.x;
    const int warp = tid >> 5, lane = tid & 31;
    const int qr = lane >> 2, qc = lane & 3;
    const int wm = (warp >> 1) * 32;
    const int wn = (warp & 1) * 32;
    const int m0 = blockIdx.y * 128, n0 = blockIdx.x * 64;

    int xrow[4], xch[4];
    #pragma unroll
    for (int i = 0; i < 4; i++) {
        int s = tid + i*256;
        xrow[i] = s >> 3;  xch[i] = s & 7;   // 8 float4-chunks per 32-f32 row
    }

    float4 xbuf[4], wbuf[2];
    auto ldreg = [&](int k0) {
        #pragma unroll
        for (int i = 0; i < 4; i++)
            xbuf[i] = *(const float4*)(X + (size_t)(m0 + xrow[i])*DMODEL + k0 + xch[i]*4);
        #pragma unroll
        for (int i = 0; i < 2; i++)
            wbuf[i] = *(const float4*)(W + (size_t)(n0 + xrow[i])*DMODEL + k0 + xch[i]*4);
    };
    auto stsmem = [&](int buf) {
        #pragma unroll
        for (int i = 0; i < 4; i++)
            *(uint2*)(&sX[buf][xrow[i]*GKP + xch[i]*2]) =
                make_uint2(pk(xbuf[i].x, xbuf[i].y), pk(xbuf[i].z, xbuf[i].w));
        #pragma unroll
        for (int i = 0; i < 2; i++)
            *(uint2*)(&sW[buf][xrow[i]*GKP + xch[i]*2]) =
                make_uint2(pk(wbuf[i].x, wbuf[i].y), pk(wbuf[i].z, wbuf[i].w));
    };

    float c[2][4][4] = {};

    ldreg(0);
    #pragma unroll 1
    for (int kc = 0; kc < DMODEL/32; kc++) {
        stsmem(kc & 1);
        __syncthreads();
        if (kc + 1 < DMODEL/32) ldreg((kc+1)*32);

        const uint32_t* Xb = sX[kc & 1];
        const uint32_t* Wb = sW[kc & 1];
        #pragma unroll
        for (int kk = 0; kk < 2; kk++) {
            uint32_t a[2][4];
            #pragma unroll
            for (int mi = 0; mi < 2; mi++) {
                int r = wm + mi*16 + qr;
                a[mi][0] = Xb[(r  )*GKP + kk*8 + qc];
                a[mi][1] = Xb[(r+8)*GKP + kk*8 + qc];
                a[mi][2] = Xb[(r  )*GKP + kk*8 + qc + 4];
                a[mi][3] = Xb[(r+8)*GKP + kk*8 + qc + 4];
            }
            #pragma unroll
            for (int nj = 0; nj < 4; nj++) {
                int r = wn + nj*8 + qr;
                uint32_t b0 = Wb[r*GKP + kk*8 + qc];
                uint32_t b1 = Wb[r*GKP + kk*8 + qc + 4];
                mma16(c[0][nj], a[0][0], a[0][1], a[0][2], a[0][3], b0, b1);
                mma16(c[1][nj], a[1][0], a[1][1], a[1][2], a[1][3], b0, b1);
            }
        }
        __syncthreads();
    }

    #pragma unroll
    for (int mi = 0; mi < 2; mi++) {
        int row0 = m0 + wm + mi*16 + qr;
        int row1 = row0 + 8;
        int bi0 = row0 >> 11, l0 = row0 & 2047;
        int bi1 = row1 >> 11, l1 = row1 & 2047;
        #pragma unroll
        for (int nj = 0; nj < 4; nj++) {
            int col = n0 + wn + nj*8 + qc*2;
            float b0 = B[col], b1 = B[col+1];
            float v00 = c[mi][nj][0] + b0, v01 = c[mi][nj][1] + b1;
            float v10 = c[mi][nj][2] + b0, v11 = c[mi][nj][3] + b1;
            int h = col >> 6, d = col & 63;
            if (mode == 1) {
                v00 *= 0.125f; v01 *= 0.125f; v10 *= 0.125f; v11 *= 0.125f;
            }
            if (mode == 3) {
                float c0 = args.coef[row0], c1 = args.coef[row1];
                __half* p = Y + ((size_t)(bi0*NHEAD + h)*DHEAD + d)*LL;  // [bh][d][l]
                p[l0]        = __float2half(v00*c0);
                p[LL + l0]   = __float2half(v01*c0);
                p[l1]        = __float2half(v10*c1);
                p[LL + l1]   = __float2half(v11*c1);
                (void)bi1;
            } else {
                *(__half2*)(Y + ((size_t)(bi0*NHEAD + h)*LL + l0)*DHEAD + d) =
                    __floats2half2_rn(v00, v01);
                *(__half2*)(Y + ((size_t)(bi1*NHEAD + h)*LL + l1)*DHEAD + d) =
                    __floats2half2_rn(v10, v11);
            }
        }
    }
}

// ---------------------------------------------------------------------------
// FP16 TC GEMM (output): Y = Xh @ W^T + bias.  fp16 X, f32 W -> f32 Y.
// ---------------------------------------------------------------------------
__global__ void __launch_bounds__(256) gemm_out(
    const __half* __restrict__ Xh, const float* __restrict__ W,
    const float* __restrict__ B, float* __restrict__ Y)
{
    __shared__ uint32_t sX[2][128*GKP];
    __shared__ uint32_t sW[2][64*GKP];

    const int tid  = threadIdx.x;
    const int warp = tid >> 5, lane = tid & 31;
    const int qr = lane >> 2, qc = lane & 3;
    const int wm = (warp >> 1) * 32;
    const int wn = (warp & 1) * 32;
    const int m0 = blockIdx.y * 128, n0 = blockIdx.x * 64;

    int xrow[2], xch[2], wrow[2], wch[2];
    #pragma unroll
    for (int i = 0; i < 2; i++) {
        int s = tid + i*256;
        xrow[i] = s >> 2;  xch[i] = s & 3;   // 4 uint4-chunks per 32-half row
        wrow[i] = s >> 3;  wch[i] = s & 7;
    }

    uint4 xbuf[2];
    float4 wbuf[2];
    auto ldreg = [&](int k0) {
        #pragma unroll
        for (int i = 0; i < 2; i++) {
            xbuf[i] = *(const uint4*)(Xh + (size_t)(m0 + xrow[i])*DMODEL + k0 + xch[i]*8);
            wbuf[i] = *(const float4*)(W + (size_t)(n0 + wrow[i])*DMODEL + k0 + wch[i]*4);
        }
    };
    auto stsmem = [&](int buf) {
        #pragma unroll
        for (int i = 0; i < 2; i++) {
            *(uint4*)(&sX[buf][xrow[i]*GKP + xch[i]*4]) = xbuf[i];
            *(uint2*)(&sW[buf][wrow[i]*GKP + wch[i]*2]) =
                make_uint2(pk(wbuf[i].x, wbuf[i].y), pk(wbuf[i].z, wbuf[i].w));
        }
    };

    float c[2][4][4] = {};

    ldreg(0);
    #pragma unroll 1
    for (int kc = 0; kc < DMODEL/32; kc++) {
        stsmem(kc & 1);
        __syncthreads();
        if (kc + 1 < DMODEL/32) ldreg((kc+1)*32);

        const uint32_t* Xb = sX[kc & 1];
        const uint32_t* Wb = sW[kc & 1];
        #pragma unroll
        for (int kk = 0; kk < 2; kk++) {
            uint32_t a[2][4];
            #pragma unroll
            for (int mi = 0; mi < 2; mi++) {
                int r = wm + mi*16 + qr;
                a[mi][0] = Xb[(r  )*GKP + kk*8 + qc];
                a[mi][1] = Xb[(r+8)*GKP + kk*8 + qc];
                a[mi][2] = Xb[(r  )*GKP + kk*8 + qc + 4];
                a[mi][3] = Xb[(r+8)*GKP + kk*8 + qc + 4];
            }
            #pragma unroll
            for (int nj = 0; nj < 4; nj++) {
                int r = wn + nj*8 + qr;
                uint32_t b0 = Wb[r*GKP + kk*8 + qc];
                uint32_t b1 = Wb[r*GKP + kk*8 + qc + 4];
                mma16(c[0][nj], a[0][0], a[0][1], a[0][2], a[0][3], b0, b1);
                mma16(c[1][nj], a[1][0], a[1][1], a[1][2], a[1][3], b0, b1);
            }
        }
        __syncthreads();
    }

    #pragma unroll
    for (int mi = 0; mi < 2; mi++) {
        int row0 = m0 + wm + mi*16 + qr;
        int row1 = row0 + 8;
        #pragma unroll
        for (int nj = 0; nj < 4; nj++) {
            int col = n0 + wn + nj*8 + qc*2;
            float b0 = B[col], b1 = B[col+1];
            *(float2*)(Y + (size_t)row0*DMODEL + col) =
                make_float2(c[mi][nj][0] + b0, c[mi][nj][1] + b1);
            *(float2*)(Y + (size_t)row1*DMODEL + col) =
                make_float2(c[mi][nj][2] + b0, c[mi][nj][3] + b1);
        }
    }
}

// ---------------------------------------------------------------------------
// Fused attention v5: fp16 m16n8k16.  BM=128, BN=64, 256 threads, 2 CTAs/SM.
// P c-fragments feed PV A-fragments directly (no shuffles, no smem P).
// V pre-transposed/pre-scaled by producer; K/V/coef via cp.async double buffer.
// ---------------------------------------------------------------------------
#define AP 36                 // pitch words (64 halves = 32 words + 4 pad; 144B)
#define KT (64*AP)
#define ATTN_SMEM ((4*KT + 2*64) * 4)

__global__ void __launch_bounds__(256, 2) attn_kernel()
{
    extern __shared__ uint32_t smu[];
    uint32_t* Ks  = smu;                    // [2][64key][AP]  fp16 K
    uint32_t* Vs  = smu + 2*KT;             // [2][64d][AP]    fp16 V^T (pre-scaled)
    float*    kok = (float*)(smu + 4*KT);   // [2][64]

    const int tid  = threadIdx.x;
    const int warp = tid >> 5, lane = tid & 31;
    const int qr = lane >> 2, qc = lane & 3;
    const int bh = blockIdx.y, bi = bh >> 3, h = bh & 7;
    const int q0 = blockIdx.x * 128;
    const int wrow = warp * 16;

    const __half* kbase = g_kh + (size_t)bh * LL * DHEAD;   // [l][d]
    const __half* vbase = g_vh + (size_t)bh * DHEAD * LL;   // [d][l]
    const float*  cbase = g_coef + bi*LL;

    const uint32_t sK = (uint32_t)__cvta_generic_to_shared(Ks);
    const uint32_t sV = (uint32_t)__cvta_generic_to_shared(Vs);
    const uint32_t sC = (uint32_t)__cvta_generic_to_shared(kok);

    int lr[2], lc[2];
    #pragma unroll
    for (int i = 0; i < 2; i++) {
        int s = tid + i*256;
        lr[i] = s >> 3;  lc[i] = s & 7;     // 8 x 16B chunks per 128B row
    }

    auto prefetch = [&](int buf, int k0) {
        #pragma unroll
        for (int i = 0; i < 2; i++) {
            cp_async16(sK + (buf*KT + lr[i]*AP + lc[i]*4)*4,
                       kbase + (size_t)(k0 + lr[i])*DHEAD + lc[i]*8);
            cp_async16(sV + (buf*KT + lr[i]*AP + lc[i]*4)*4,
                       vbase + (size_t)lr[i]*LL + k0 + lc[i]*8);
        }
        if (tid < 16)
            cp_async16(sC + (buf*64 + tid*4)*4, cbase + k0 + tid*4);
        asm volatile("cp.async.commit_group;");
    };

    prefetch(0, 0);

    // ---- Q fragments straight from gmem (fp16, pre-scaled 1/8) ----
    const uint32_t* qrow0 =
        (const uint32_t*)(g_qh + ((size_t)bh*LL + q0 + wrow + qr)*DHEAD);
    const uint32_t* qrow1 = qrow0 + 8*(DHEAD/2);
    uint32_t aQ[4][4];
    #pragma unroll
    for (int kk = 0; kk < 4; kk++) {
        aQ[kk][0] = qrow0[kk*8 + qc];
        aQ[kk][1] = qrow1[kk*8 + qc];
        aQ[kk][2] = qrow0[kk*8 + qc + 4];
        aQ[kk][3] = qrow1[kk*8 + qc + 4];
    }
    const bool q0ok = (cbase[q0 + wrow + qr]     != 0.0f);
    const bool q1ok = (cbase[q0 + wrow + qr + 8] != 0.0f);

    float o[8][4] = {};
    float m0 = -1e30f, m1 = -1e30f, l0 = 0.0f, l1 = 0.0f;

    #pragma unroll 1
    for (int t = 0; t < LL/64; t++) {
        asm volatile("cp.async.wait_group 0;");
        __syncthreads();
        if (t + 1 < LL/64) prefetch((t+1) & 1, (t+1)*64);

        const uint32_t* Kb = Ks + (t & 1)*KT;
        const uint32_t* Vb = Vs + (t & 1)*KT;
        const float*    kb = kok + (t & 1)*64;

        // ---- S = (Q/8) @ K^T  (4 k16-chunks x 8 n-tiles) ----
        float s[8][4] = {};
        #pragma unroll
        for (int kk = 0; kk < 4; kk++) {
            #pragma unroll
            for (int j = 0; j < 8; j++) {
                uint32_t b0 = Kb[(j*8+qr)*AP + kk*8 + qc];
                uint32_t b1 = Kb[(j*8+qr)*AP + kk*8 + qc + 4];
                mma16(s[j], aQ[kk][0], aQ[kk][1], aQ[kk][2], aQ[kk][3], b0, b1);
            }
        }

        // ---- mask (c-frag cols = j*8 + 2qc, 2qc+1) ----
        #pragma unroll
        for (int j = 0; j < 8; j++) {
            bool kc0 = (kb[j*8 + qc*2    ] != 0.0f);
            bool kc1 = (kb[j*8 + qc*2 + 1] != 0.0f);
            if (!(q0ok && kc0)) s[j][0] = -10000.0f;
            if (!(q0ok && kc1)) s[j][1] = -10000.0f;
            if (!(q1ok && kc0)) s[j][2] = -10000.0f;
            if (!(q1ok && kc1)) s[j][3] = -10000.0f;
        }

        // ---- online softmax: row max ----
        float mx0 = -1e30f, mx1 = -1e30f;
        #pragma unroll
        for (int j = 0; j < 8; j++) {
            mx0 = fmaxf(mx0, fmaxf(s[j][0], s[j][1]));
            mx1 = fmaxf(mx1, fmaxf(s[j][2], s[j][3]));
        }
        mx0 = fmaxf(mx0, __shfl_xor_sync(0xffffffffu, mx0, 1));
        mx0 = fmaxf(mx0, __shfl_xor_sync(0xffffffffu, mx0, 2));
        mx1 = fmaxf(mx1, __shfl_xor_sync(0xffffffffu, mx1, 1));
        mx1 = fmaxf(mx1, __shfl_xor_sync(0xffffffffu, mx1, 2));
        float nm0 = fmaxf(m0, mx0), nm1 = fmaxf(m1, mx1);
        float sc0 = __expf(m0 - nm0), sc1 = __expf(m1 - nm1);
        m0 = nm0; m1 = nm1;

        #pragma unroll
        for (int j = 0; j < 8; j++) {
            o[j][0] *= sc0; o[j][1] *= sc0;
            o[j][2] *= sc1; o[j][3] *= sc1;
        }

        // ---- exp -> fp16 A-fragments (direct pack) -> PV mma ----
        float rs0 = 0.0f, rs1 = 0.0f;
        #pragma unroll
        for (int jj = 0; jj < 4; jj++) {      // seq k16-chunk = n-tiles 2jj, 2jj+1
            float p00 = __expf(s[2*jj  ][0] - nm0);
            float p01 = __expf(s[2*jj  ][1] - nm0);
            float p02 = __expf(s[2*jj  ][2] - nm1);
            float p03 = __expf(s[2*jj  ][3] - nm1);
            float p10 = __expf(s[2*jj+1][0] - nm0);
            float p11 = __expf(s[2*jj+1][1] - nm0);
            float p12 = __expf(s[2*jj+1][2] - nm1);
            float p13 = __expf(s[2*jj+1][3] - nm1);
            rs0 += p00 + p01 + p10 + p11;
            rs1 += p02 + p03 + p12 + p13;

            uint32_t a0 = pk(p00, p01);   // row qr,   k = 16jj+2qc,+1
            uint32_t a1 = pk(p02, p03);   // row qr+8
            uint32_t a2 = pk(p10, p11);   // row qr,   k = 16jj+8+2qc,+1
            uint32_t a3 = pk(p12, p13);   // row qr+8

            #pragma unroll
            for (int nj = 0; nj < 8; nj++) {
                uint32_t b0 = Vb[(nj*8+qr)*AP + jj*8 + qc];
                uint32_t b1 = Vb[(nj*8+qr)*AP + jj*8 + qc + 4];
                mma16(o[nj], a0, a1, a2, a3, b0, b1);
            }
        }
        rs0 += __shfl_xor_sync(0xffffffffu, rs0, 1);
        rs0 += __shfl_xor_sync(0xffffffffu, rs0, 2);
        rs1 += __shfl_xor_sync(0xffffffffu, rs1, 1);
        rs1 += __shfl_xor_sync(0xffffffffu, rs1, 2);
        l0 = l0*sc0 + rs0;
        l1 = l1*sc1 + rs1;
    }

    // ---- epilogue: normalize, write fp16 [l][512] ----
    float inv0 = 1.0f / l0, inv1 = 1.0f / l1;
    int r0 = q0 + wrow + qr, r1 = r0 + 8;
    #pragma unroll
    for (int j = 0; j < 8; j++) {
        int d = h*64 + j*8 + qc*2;
        *(__half2*)(g_attnh + ((size_t)(bi*LL + r0))*DMODEL + d) =
            __floats2half2_rn(o[j][0]*inv0, o[j][1]*inv0);
        *(__half2*)(g_attnh + ((size_t)(bi*LL + r1))*DMODEL + d) =
            __floats2half2_rn(o[j][2]*inv1, o[j][3]*inv1);
    }
}

// ---------------------------------------------------------------------------
extern "C" void kernel_launch(void* const* d_in, const int* in_sizes, int n_in,
                              void* d_out, int out_size)
{
    const float* q  = (const float*)d_in[0];
    const float* k  = (const float*)d_in[1];
    const float* v  = (const float*)d_in[2];
    const float* tm = (const float*)d_in[3];
    const float* am = (const float*)d_in[4];
    const float* wq = (const float*)d_in[6];
    const float* bq = (const float*)d_in[7];
    const float* wk = (const float*)d_in[8];
    const float* bk = (const float*)d_in[9];
    const float* wv = (const float*)d_in[10];
    const float* bv = (const float*)d_in[11];
    const float* wo = (const float*)d_in[12];
    const float* bo = (const float*)d_in[13];
    float* out = (float*)d_out;

    __half *gq, *gk, *gv, *gattn;
    float *gcoef;
    cudaGetSymbolAddress((void**)&gq,    g_qh);
    cudaGetSymbolAddress((void**)&gk,    g_kh);
    cudaGetSymbolAddress((void**)&gv,    g_vh);
    cudaGetSymbolAddress((void**)&gattn, g_attnh);
    cudaGetSymbolAddress((void**)&gcoef, g_coef);

    cudaFuncSetAttribute(attn_kernel, cudaFuncAttributeMaxDynamicSharedMemorySize, ATTN_SMEM);

    coef_kernel<<<2, 1024>>>(tm, am);   // must precede QKV (V epilogue reads coef)

    QkvArgs qkv;
    qkv.X[0] = q;  qkv.X[1] = k;  qkv.X[2] = v;
    qkv.W[0] = wq; qkv.W[1] = wk; qkv.W[2] = wv;
    qkv.bias[0] = bq; qkv.bias[1] = bk; qkv.bias[2] = bv;
    qkv.Y[0] = gq; qkv.Y[1] = gk; qkv.Y[2] = gv;
    qkv.mode[0] = 1; qkv.mode[1] = 2; qkv.mode[2] = 3;
    qkv.coef = gcoef;
    gemm_qkv<<<dim3(8, 32, 3), 256>>>(qkv);

    attn_kernel<<<dim3(16, 16), 256, ATTN_SMEM>>>();

    gemm_out<<<dim3(8, 32), 256>>>(gattn, wo, bo, out);
}